// round 5
// baseline (speedup 1.0000x reference)
#include <cuda_runtime.h>
#include <cuda_bf16.h>
#include <math.h>
#include <stdint.h>

#define B_   64
#define C_   1000
#define F_   2048
#define KSA  8      // split-K for mega hmma gemm
#define KSM  16     // split-K for mem gemm
#define KSC  32     // split-K for cos gemm
#define CP   1024   // padded C stride

// ---------------- scratch ----------------
__device__ float g_p_dot[KSA][B_ * CP];
__device__ float g_p_hall[KSA][B_ * CP];
__device__ float g_p_sel[KSA][B_ * F_];
__device__ float g_p_mem[KSM][B_ * F_];
__device__ float g_p_cos[KSC][B_ * CP];
__device__ float g_hall[B_ * CP];
__device__ float g_vm[B_ * CP];
__device__ float g_feat[B_ * F_];
__device__ float g_cn2[CP];
__device__ float g_wn[CP];
__device__ float g_xn2[B_];
__device__ float g_reach[B_];
__device__ float g_scale[B_];

// ================= bf16 hi/lo helpers =================
// hi = fp32 truncated to bf16 (top 16 bits, exact remainder), lo = rn(v - hi).
__device__ __forceinline__ void cvt_hilo(float4 v, uint2& hi, uint2& lo) {
    uint32_t bx = __float_as_uint(v.x), by = __float_as_uint(v.y);
    uint32_t bz = __float_as_uint(v.z), bw = __float_as_uint(v.w);
    hi.x = __byte_perm(bx, by, 0x7632);   // {x_hi16 (low), y_hi16 (high)}
    hi.y = __byte_perm(bz, bw, 0x7632);
    float rx = v.x - __uint_as_float(bx & 0xffff0000u);
    float ry = v.y - __uint_as_float(by & 0xffff0000u);
    float rz = v.z - __uint_as_float(bz & 0xffff0000u);
    float rw = v.w - __uint_as_float(bw & 0xffff0000u);
    asm("cvt.rn.bf16x2.f32 %0, %1, %2;" : "=r"(lo.x) : "f"(ry), "f"(rx));
    asm("cvt.rn.bf16x2.f32 %0, %1, %2;" : "=r"(lo.y) : "f"(rw), "f"(rz));
}

__device__ __forceinline__ void mma16816(float* d,
                                         uint32_t a0, uint32_t a1, uint32_t a2, uint32_t a3,
                                         uint32_t b0, uint32_t b1) {
    asm volatile("mma.sync.aligned.m16n8k16.row.col.f32.bf16.bf16.f32 "
        "{%0,%1,%2,%3}, {%4,%5,%6,%7}, {%8,%9}, {%0,%1,%2,%3};"
        : "+f"(d[0]), "+f"(d[1]), "+f"(d[2]), "+f"(d[3])
        : "r"(a0), "r"(a1), "r"(a2), "r"(a3), "r"(b0), "r"(b1));
}

// ---------------- mega HMMA GEMM: x @ [centroids; W_hall; W_sel]^T ----------------
// grid (64, KSA), 128 threads. 64x64 out tile, k-chunk 256 (4 subtiles of 64).
// hi/lo split: acc += Ah*Bh + Ah*Bl + Al*Bh  (fp32 accum in mma).
__global__ __launch_bounds__(128) void mega_hmma(const float* __restrict__ x,
                                                 const float* __restrict__ centroids,
                                                 const float* __restrict__ W_hall,
                                                 const float* __restrict__ W_sel) {
    __shared__ __nv_bfloat16 Ah[64][72], Al[64][72], Bh[64][72], Bl[64][72];
    const int tid  = threadIdx.x, lane = tid & 31, warp = tid >> 5;
    const int t = blockIdx.x, ks = blockIdx.y;

    const float* Bsrc; float* P; int Nn, n0, ldp;
    if (t < 16)      { Bsrc = centroids; P = &g_p_dot[ks][0];  Nn = C_; n0 = t * 64;        ldp = CP; }
    else if (t < 32) { Bsrc = W_hall;    P = &g_p_hall[ks][0]; Nn = C_; n0 = (t - 16) * 64; ldp = CP; }
    else             { Bsrc = W_sel;     P = &g_p_sel[ks][0];  Nn = F_; n0 = (t - 32) * 64; ldp = F_; }
    const int k0 = ks * 256;

    float acc[8][4];
#pragma unroll
    for (int i = 0; i < 8; i++)
#pragma unroll
        for (int j = 0; j < 4; j++) acc[i][j] = 0.f;

    const int  lrow = tid >> 1;                 // loader row 0..63
    const int  lcb  = (tid & 1) * 32;           // loader col base (floats)
    const bool bval = (n0 + lrow) < Nn;
    const float4* arow = (const float4*)(x + (size_t)lrow * F_);
    const float4* brow = (const float4*)(Bsrc + (size_t)(n0 + lrow) * F_);

    const int m0 = warp * 16;
    const int fr = lane >> 2, fc = (lane & 3) * 2;

    for (int sub = 0; sub < 4; sub++) {
        const int kb = k0 + sub * 64;
        // ---- load + convert 64x64 fp32 -> bf16 hi/lo (A and B) ----
#pragma unroll
        for (int i = 0; i < 8; i++) {
            uint2 hi, lo;
            float4 va = arow[(kb + lcb) / 4 + i];
            cvt_hilo(va, hi, lo);
            *(uint2*)&Ah[lrow][lcb + i * 4] = hi;
            *(uint2*)&Al[lrow][lcb + i * 4] = lo;
            float4 vb = bval ? brow[(kb + lcb) / 4 + i] : make_float4(0.f, 0.f, 0.f, 0.f);
            cvt_hilo(vb, hi, lo);
            *(uint2*)&Bh[lrow][lcb + i * 4] = hi;
            *(uint2*)&Bl[lrow][lcb + i * 4] = lo;
        }
        __syncthreads();
        // ---- 4 k16 steps, 8 n-tiles, 3 mma each ----
#pragma unroll
        for (int kk = 0; kk < 4; kk++) {
            const int kc = kk * 16 + fc;
            uint32_t ah0 = *(const uint32_t*)&Ah[m0 + fr][kc];
            uint32_t ah1 = *(const uint32_t*)&Ah[m0 + fr + 8][kc];
            uint32_t ah2 = *(const uint32_t*)&Ah[m0 + fr][kc + 8];
            uint32_t ah3 = *(const uint32_t*)&Ah[m0 + fr + 8][kc + 8];
            uint32_t al0 = *(const uint32_t*)&Al[m0 + fr][kc];
            uint32_t al1 = *(const uint32_t*)&Al[m0 + fr + 8][kc];
            uint32_t al2 = *(const uint32_t*)&Al[m0 + fr][kc + 8];
            uint32_t al3 = *(const uint32_t*)&Al[m0 + fr + 8][kc + 8];
#pragma unroll
            for (int nt = 0; nt < 8; nt++) {
                const int bn = nt * 8 + fr;
                uint32_t bh0 = *(const uint32_t*)&Bh[bn][kc];
                uint32_t bh1 = *(const uint32_t*)&Bh[bn][kc + 8];
                uint32_t bl0 = *(const uint32_t*)&Bl[bn][kc];
                uint32_t bl1 = *(const uint32_t*)&Bl[bn][kc + 8];
                mma16816(acc[nt], ah0, ah1, ah2, ah3, bh0, bh1);
                mma16816(acc[nt], ah0, ah1, ah2, ah3, bl0, bl1);
                mma16816(acc[nt], al0, al1, al2, al3, bh0, bh1);
            }
        }
        __syncthreads();
    }
    // ---- store D fragments ----
#pragma unroll
    for (int nt = 0; nt < 8; nt++) {
        const int n = n0 + nt * 8 + fc;
        if (n < Nn) {
            *(float2*)&P[(size_t)(m0 + fr) * ldp + n]     = make_float2(acc[nt][0], acc[nt][1]);
            *(float2*)&P[(size_t)(m0 + fr + 8) * ldp + n] = make_float2(acc[nt][2], acc[nt][3]);
        }
    }
}

// ================= fp32 FFMA2 path (mem / cos GEMMs) =================
__device__ __forceinline__ unsigned long long pack2(float v) {
    unsigned long long r;
    asm("mov.b64 %0, {%1, %1};" : "=l"(r) : "f"(v));
    return r;
}
__device__ __forceinline__ void fma2(unsigned long long& d, unsigned long long a, unsigned long long b) {
    asm("fma.rn.f32x2 %0, %1, %2, %0;" : "+l"(d) : "l"(a), "l"(b));
}

__device__ __forceinline__ void tile_mma(const float (*As)[68], const float (*Bs)[68],
                                         int ty, int tx, unsigned long long acc[4][4]) {
#pragma unroll
    for (int kk = 0; kk < 16; kk++) {
        float4 av = *(const float4*)&As[kk][ty * 4];
        ulonglong2 bp = *(const ulonglong2*)&Bs[kk][tx * 8];
        ulonglong2 bq = *(const ulonglong2*)&Bs[kk][tx * 8 + 4];
        unsigned long long a0 = pack2(av.x), a1 = pack2(av.y), a2 = pack2(av.z), a3 = pack2(av.w);
        fma2(acc[0][0], a0, bp.x); fma2(acc[0][1], a0, bp.y); fma2(acc[0][2], a0, bq.x); fma2(acc[0][3], a0, bq.y);
        fma2(acc[1][0], a1, bp.x); fma2(acc[1][1], a1, bp.y); fma2(acc[1][2], a1, bq.x); fma2(acc[1][3], a1, bq.y);
        fma2(acc[2][0], a2, bp.x); fma2(acc[2][1], a2, bp.y); fma2(acc[2][2], a2, bq.x); fma2(acc[2][3], a2, bq.y);
        fma2(acc[3][0], a3, bp.x); fma2(acc[3][1], a3, bp.y); fma2(acc[3][2], a3, bq.x); fma2(acc[3][3], a3, bq.y);
    }
}

__device__ __forceinline__ void gemm64_nt(const float* __restrict__ A, int lda,
                                          const float* __restrict__ Bm, int ldb,
                                          float* __restrict__ P, int ldp,
                                          int N, int n0, int k0, int klen) {
    __shared__ float As[2][16][68];
    __shared__ float Bs[2][16][68];
    const int tid = threadIdx.x;
    const int tx  = tid & 7;
    const int ty  = tid >> 3;
    const int lr  = tid >> 2;
    const int lkq = (tid & 3) * 4;
    const int br0 = n0 + lr, br1 = n0 + lr + 32;
    const bool v0 = br0 < N, v1 = br1 < N;

    unsigned long long acc[4][4];
#pragma unroll
    for (int i = 0; i < 4; i++)
#pragma unroll
        for (int j = 0; j < 4; j++) acc[i][j] = 0ull;

    {
        float4 a0 = *(const float4*)&A[(size_t)lr * lda + k0 + lkq];
        float4 a1 = *(const float4*)&A[(size_t)(lr + 32) * lda + k0 + lkq];
        float4 b0 = v0 ? *(const float4*)&Bm[(size_t)br0 * ldb + k0 + lkq] : make_float4(0.f,0.f,0.f,0.f);
        float4 b1 = v1 ? *(const float4*)&Bm[(size_t)br1 * ldb + k0 + lkq] : make_float4(0.f,0.f,0.f,0.f);
        As[0][lkq+0][lr] = a0.x; As[0][lkq+1][lr] = a0.y; As[0][lkq+2][lr] = a0.z; As[0][lkq+3][lr] = a0.w;
        As[0][lkq+0][lr+32] = a1.x; As[0][lkq+1][lr+32] = a1.y; As[0][lkq+2][lr+32] = a1.z; As[0][lkq+3][lr+32] = a1.w;
        Bs[0][lkq+0][lr] = b0.x; Bs[0][lkq+1][lr] = b0.y; Bs[0][lkq+2][lr] = b0.z; Bs[0][lkq+3][lr] = b0.w;
        Bs[0][lkq+0][lr+32] = b1.x; Bs[0][lkq+1][lr+32] = b1.y; Bs[0][lkq+2][lr+32] = b1.z; Bs[0][lkq+3][lr+32] = b1.w;
    }
    __syncthreads();

    int buf = 0;
    for (int kb = k0; kb < k0 + klen; kb += 16) {
        const bool hn = (kb + 16) < k0 + klen;
        float4 na0, na1, nb0, nb1;
        if (hn) {
            int kn = kb + 16;
            na0 = *(const float4*)&A[(size_t)lr * lda + kn + lkq];
            na1 = *(const float4*)&A[(size_t)(lr + 32) * lda + kn + lkq];
            nb0 = v0 ? *(const float4*)&Bm[(size_t)br0 * ldb + kn + lkq] : make_float4(0.f,0.f,0.f,0.f);
            nb1 = v1 ? *(const float4*)&Bm[(size_t)br1 * ldb + kn + lkq] : make_float4(0.f,0.f,0.f,0.f);
        }
        tile_mma(As[buf], Bs[buf], ty, tx, acc);
        if (hn) {
            int nb = buf ^ 1;
            As[nb][lkq+0][lr] = na0.x; As[nb][lkq+1][lr] = na0.y; As[nb][lkq+2][lr] = na0.z; As[nb][lkq+3][lr] = na0.w;
            As[nb][lkq+0][lr+32] = na1.x; As[nb][lkq+1][lr+32] = na1.y; As[nb][lkq+2][lr+32] = na1.z; As[nb][lkq+3][lr+32] = na1.w;
            Bs[nb][lkq+0][lr] = nb0.x; Bs[nb][lkq+1][lr] = nb0.y; Bs[nb][lkq+2][lr] = nb0.z; Bs[nb][lkq+3][lr] = nb0.w;
            Bs[nb][lkq+0][lr+32] = nb1.x; Bs[nb][lkq+1][lr+32] = nb1.y; Bs[nb][lkq+2][lr+32] = nb1.z; Bs[nb][lkq+3][lr+32] = nb1.w;
        }
        __syncthreads();
        buf ^= 1;
    }

    const int n = n0 + tx * 8;
    if (n < N) {
#pragma unroll
        for (int i = 0; i < 4; i++) {
            int m = ty * 4 + i;
            *(ulonglong2*)&P[(size_t)m * ldp + n]     = make_ulonglong2(acc[i][0], acc[i][1]);
            *(ulonglong2*)&P[(size_t)m * ldp + n + 4] = make_ulonglong2(acc[i][2], acc[i][3]);
        }
    }
}

__global__ __launch_bounds__(128) void cos_gemm(const float* __restrict__ W_cos) {
    gemm64_nt(g_feat, F_, W_cos, F_, g_p_cos[blockIdx.y], CP, C_,
              blockIdx.x * 64, blockIdx.y * (F_ / KSC), F_ / KSC);
}

__global__ __launch_bounds__(128) void mem_gemm(const float* __restrict__ centroids) {
    __shared__ float As[2][16][68];
    __shared__ float Bs[2][16][68];
    const int n0  = blockIdx.x * 64;
    const int k0  = blockIdx.y * 64;
    const int tid = threadIdx.x;
    const int tx  = tid & 7, ty = tid >> 3;
    const int lr  = tid >> 2, lkq = (tid & 3) * 4;
    const int bk  = tid >> 3;
    const int bnq = (tid & 7) * 8;

    unsigned long long acc[4][4];
#pragma unroll
    for (int i = 0; i < 4; i++)
#pragma unroll
        for (int j = 0; j < 4; j++) acc[i][j] = 0ull;

    {
        float4 a0 = *(const float4*)&g_vm[lr * CP + k0 + lkq];
        float4 a1 = *(const float4*)&g_vm[(lr + 32) * CP + k0 + lkq];
        int k = k0 + bk;
        float4 b0 = make_float4(0.f,0.f,0.f,0.f), b1 = b0;
        if (k < C_) {
            b0 = *(const float4*)&centroids[(size_t)k * F_ + n0 + bnq];
            b1 = *(const float4*)&centroids[(size_t)k * F_ + n0 + bnq + 4];
        }
        As[0][lkq+0][lr] = a0.x; As[0][lkq+1][lr] = a0.y; As[0][lkq+2][lr] = a0.z; As[0][lkq+3][lr] = a0.w;
        As[0][lkq+0][lr+32] = a1.x; As[0][lkq+1][lr+32] = a1.y; As[0][lkq+2][lr+32] = a1.z; As[0][lkq+3][lr+32] = a1.w;
        *(float4*)&Bs[0][bk][bnq]     = b0;
        *(float4*)&Bs[0][bk][bnq + 4] = b1;
    }
    __syncthreads();

    int buf = 0;
    for (int kb = k0; kb < k0 + 64; kb += 16) {
        const bool hn = (kb + 16) < k0 + 64;
        float4 na0, na1, nb0, nb1;
        if (hn) {
            int kn = kb + 16;
            na0 = *(const float4*)&g_vm[lr * CP + kn + lkq];
            na1 = *(const float4*)&g_vm[(lr + 32) * CP + kn + lkq];
            int k = kn + bk;
            nb0 = make_float4(0.f,0.f,0.f,0.f); nb1 = nb0;
            if (k < C_) {
                nb0 = *(const float4*)&centroids[(size_t)k * F_ + n0 + bnq];
                nb1 = *(const float4*)&centroids[(size_t)k * F_ + n0 + bnq + 4];
            }
        }
        tile_mma(As[buf], Bs[buf], ty, tx, acc);
        if (hn) {
            int nb = buf ^ 1;
            As[nb][lkq+0][lr] = na0.x; As[nb][lkq+1][lr] = na0.y; As[nb][lkq+2][lr] = na0.z; As[nb][lkq+3][lr] = na0.w;
            As[nb][lkq+0][lr+32] = na1.x; As[nb][lkq+1][lr+32] = na1.y; As[nb][lkq+2][lr+32] = na1.z; As[nb][lkq+3][lr+32] = na1.w;
            *(float4*)&Bs[nb][bk][bnq]     = nb0;
            *(float4*)&Bs[nb][bk][bnq + 4] = nb1;
        }
        __syncthreads();
        buf ^= 1;
    }

    float* P = g_p_mem[blockIdx.y];
    const int n = n0 + tx * 8;
#pragma unroll
    for (int i = 0; i < 4; i++) {
        int m = ty * 4 + i;
        *(ulonglong2*)&P[(size_t)m * F_ + n]     = make_ulonglong2(acc[i][0], acc[i][1]);
        *(ulonglong2*)&P[(size_t)m * F_ + n + 4] = make_ulonglong2(acc[i][2], acc[i][3]);
    }
}

// ================= row-wise kernels =================
__global__ __launch_bounds__(256) void norms_kernel(const float* __restrict__ centroids,
                                                    const float* __restrict__ W_cos,
                                                    const float* __restrict__ x) {
    int bid = blockIdx.x;
    const float* src;
    int mode, idx;
    if (bid < C_)            { src = centroids + (size_t)bid * F_;        mode = 0; idx = bid; }
    else if (bid < 2 * C_)   { src = W_cos + (size_t)(bid - C_) * F_;     mode = 1; idx = bid - C_; }
    else                     { src = x + (size_t)(bid - 2 * C_) * F_;     mode = 2; idx = bid - 2 * C_; }
    const float4* s4 = (const float4*)src;
    float s = 0.f;
    for (int i = threadIdx.x; i < F_ / 4; i += 256) {
        float4 v = s4[i];
        s += v.x * v.x + v.y * v.y + v.z * v.z + v.w * v.w;
    }
#pragma unroll
    for (int o = 16; o > 0; o >>= 1) s += __shfl_xor_sync(0xffffffffu, s, o);
    __shared__ float red[8];
    if ((threadIdx.x & 31) == 0) red[threadIdx.x >> 5] = s;
    __syncthreads();
    if (threadIdx.x == 0) {
        float tot = 0.f;
#pragma unroll
        for (int w = 0; w < 8; w++) tot += red[w];
        if (mode == 0)      g_cn2[idx] = tot;
        else if (mode == 1) g_wn[idx]  = sqrtf(tot);
        else                g_xn2[idx] = tot;
    }
}

__global__ __launch_bounds__(256) void row_softmax_kernel(const float* __restrict__ b_hall) {
    const int b = blockIdx.x;
    const int tid = threadIdx.x;
    __shared__ float r0[256], r1[256];
    float mind2 = 1e30f, maxh = -1e30f;
    const float xn2 = g_xn2[b];
    for (int c = tid; c < C_; c += 256) {
        float dot = 0.f, hv = 0.f;
#pragma unroll
        for (int s = 0; s < KSA; s++) {
            dot += g_p_dot[s][b * CP + c];
            hv  += g_p_hall[s][b * CP + c];
        }
        hv += b_hall[c];
        g_hall[b * CP + c] = hv;
        float d2 = xn2 + g_cn2[c] - 2.f * dot;
        mind2 = fminf(mind2, d2);
        maxh  = fmaxf(maxh, hv);
    }
    r0[tid] = mind2; r1[tid] = maxh; __syncthreads();
    for (int o = 128; o > 0; o >>= 1) {
        if (tid < o) { r0[tid] = fminf(r0[tid], r0[tid + o]); r1[tid] = fmaxf(r1[tid], r1[tid + o]); }
        __syncthreads();
    }
    const float md2 = r0[0];
    const float mh  = r1[0];
    __syncthreads();
    float se = 0.f;
    for (int c = tid; c < C_; c += 256) se += __expf(g_hall[b * CP + c] - mh);
    r0[tid] = se; __syncthreads();
    for (int o = 128; o > 0; o >>= 1) {
        if (tid < o) r0[tid] += r0[tid + o];
        __syncthreads();
    }
    const float inv = 1.f / r0[0];
    for (int c = tid; c < C_; c += 256)
        g_vm[b * CP + c] = __expf(g_hall[b * CP + c] - mh) * inv;
    if (tid < CP - C_) g_vm[b * CP + C_ + tid] = 0.f;
    if (tid == 0) g_reach[b] = 10.f / sqrtf(fmaxf(md2, 1e-30f));
}

__global__ __launch_bounds__(256) void combine_kernel(const float* __restrict__ x,
                                                      const float* __restrict__ b_sel,
                                                      float* __restrict__ out, int writeFeat) {
    const int b = blockIdx.x;
    const int tid = threadIdx.x;
    __shared__ float red[256];
    const float reach = g_reach[b];
    float n2 = 0.f;
    for (int f = tid; f < F_; f += 256) {
        float mem = 0.f, sz = 0.f;
#pragma unroll
        for (int s = 0; s < KSM; s++) mem += g_p_mem[s][b * F_ + f];
#pragma unroll
        for (int s = 0; s < KSA; s++) sz  += g_p_sel[s][b * F_ + f];
        float sel  = tanhf(sz + b_sel[f]);
        float xv   = x[(size_t)b * F_ + f];
        float inf  = sel * mem;
        float feat = reach * (xv + inf);
        g_feat[b * F_ + f] = feat;
        n2 += feat * feat;
        if (writeFeat) {
            out[64000 + b * F_ + f]  = xv;
            out[195072 + b * F_ + f] = inf;
        }
    }
    red[tid] = n2; __syncthreads();
    for (int o = 128; o > 0; o >>= 1) {
        if (tid < o) red[tid] += red[tid + o];
        __syncthreads();
    }
    if (tid == 0) g_scale[b] = 16.f / (1.f + sqrtf(red[0]));
}

__global__ __launch_bounds__(256) void logits_kernel(float* __restrict__ out) {
    int i = blockIdx.x * 256 + threadIdx.x;
    if (i >= B_ * C_) return;
    int b = i / C_, c = i % C_;
    float s = 0.f;
#pragma unroll
    for (int ss = 0; ss < KSC; ss++) s += g_p_cos[ss][b * CP + c];
    out[i] = s * g_scale[b] / g_wn[c];
}

// ================= launch =================
extern "C" void kernel_launch(void* const* d_in, const int* in_sizes, int n_in,
                              void* d_out, int out_size) {
    const float* x         = (const float*)d_in[0];
    const float* centroids = (const float*)d_in[1];
    const float* W_hall    = (const float*)d_in[2];
    const float* b_hall    = (const float*)d_in[3];
    const float* W_sel     = (const float*)d_in[4];
    const float* b_sel     = (const float*)d_in[5];
    const float* W_cos     = (const float*)d_in[6];
    float* out = (float*)d_out;

    norms_kernel<<<2 * C_ + B_, 256>>>(centroids, W_cos, x);
    mega_hmma<<<dim3(64, KSA), 128>>>(x, centroids, W_hall, W_sel);
    row_softmax_kernel<<<B_, 256>>>(b_hall);
    mem_gemm<<<dim3(32, KSM), 128>>>(centroids);
    int writeFeat = (out_size >= 326144) ? 1 : 0;
    combine_kernel<<<B_, 256>>>(x, b_sel, out, writeFeat);
    cos_gemm<<<dim3(16, KSC), 128>>>(W_cos);
    logits_kernel<<<250, 256>>>(out);
}

// round 6
// speedup vs baseline: 1.6668x; 1.6668x over previous
#include <cuda_runtime.h>
#include <math.h>
#include <stdint.h>

#define B_   64
#define C_   1000
#define F_   2048
#define CP   1024
#define NB   148
typedef unsigned long long ull;

// ---------------- scratch (static __device__, no allocations) ----------------
__device__ __align__(256) float g_p_dot[16][B_ * CP];
__device__ __align__(256) float g_p_hall[16][B_ * CP];
__device__ __align__(256) float g_p_sel[16][B_ * F_];
__device__ __align__(256) float g_p_mem[16][B_ * F_];
__device__ __align__(256) float g_p_cos[32][B_ * CP];
__device__ __align__(256) float g_vm[B_ * CP];
__device__ __align__(256) float g_feat[B_ * F_];
__device__ float g_cn2[CP];
__device__ float g_wn[CP];
__device__ float g_xn2[B_];
__device__ float g_reach[B_];
__device__ float g_scale[B_];
__device__ unsigned int g_arr[8];    // zero-init (static storage)
__device__ unsigned int g_flag[8];

// ---------------- f32x2 helpers ----------------
__device__ __forceinline__ ull pack2(float v) {
    ull r;
    asm("mov.b64 %0, {%1, %1};" : "=l"(r) : "f"(v));
    return r;
}
__device__ __forceinline__ void fma2(ull& d, ull a, ull b) {
    asm("fma.rn.f32x2 %0, %1, %2, %0;" : "+l"(d) : "l"(a), "l"(b));
}

// ---------------- group barrier (256-thread group, named barrier) ----------------
__device__ __forceinline__ void gbar(int id) {
    asm volatile("bar.sync %0, 256;" :: "r"(id) : "memory");
}

// ---------------- grid sync (all NB blocks resident; graph-replay-safe) ----------------
__device__ __forceinline__ void grid_sync(int s) {
    __threadfence();
    __syncthreads();
    if (threadIdx.x == 0) {
        unsigned int before = atomicOr(&g_flag[s], 0u);
        unsigned int old = atomicAdd(&g_arr[s], 1u);
        if (old == NB - 1) {
            g_arr[s] = 0;
            __threadfence();
            atomicAdd(&g_flag[s], 1u);
        } else {
            while (atomicOr(&g_flag[s], 0u) == before) __nanosleep(64);
        }
    }
    __syncthreads();
    __threadfence();
}

// ---------------- block reductions (1024 threads, two-level) ----------------
__device__ __forceinline__ float blk_sum(float v, float* red) {
#pragma unroll
    for (int o = 16; o; o >>= 1) v += __shfl_xor_sync(0xffffffffu, v, o);
    if ((threadIdx.x & 31) == 0) red[threadIdx.x >> 5] = v;
    __syncthreads();
    if (threadIdx.x < 32) {
        float s = red[threadIdx.x];
#pragma unroll
        for (int o = 16; o; o >>= 1) s += __shfl_xor_sync(0xffffffffu, s, o);
        if (threadIdx.x == 0) red[0] = s;
    }
    __syncthreads();
    float r = red[0];
    __syncthreads();
    return r;
}
__device__ __forceinline__ float blk_min(float v, float* red) {
#pragma unroll
    for (int o = 16; o; o >>= 1) v = fminf(v, __shfl_xor_sync(0xffffffffu, v, o));
    if ((threadIdx.x & 31) == 0) red[threadIdx.x >> 5] = v;
    __syncthreads();
    if (threadIdx.x < 32) {
        float s = red[threadIdx.x];
#pragma unroll
        for (int o = 16; o; o >>= 1) s = fminf(s, __shfl_xor_sync(0xffffffffu, s, o));
        if (threadIdx.x == 0) red[0] = s;
    }
    __syncthreads();
    float r = red[0];
    __syncthreads();
    return r;
}
__device__ __forceinline__ float blk_max(float v, float* red) {
#pragma unroll
    for (int o = 16; o; o >>= 1) v = fmaxf(v, __shfl_xor_sync(0xffffffffu, v, o));
    if ((threadIdx.x & 31) == 0) red[threadIdx.x >> 5] = v;
    __syncthreads();
    if (threadIdx.x < 32) {
        float s = red[threadIdx.x];
#pragma unroll
        for (int o = 16; o; o >>= 1) s = fmaxf(s, __shfl_xor_sync(0xffffffffu, s, o));
        if (threadIdx.x == 0) red[0] = s;
    }
    __syncthreads();
    float r = red[0];
    __syncthreads();
    return r;
}

// ---------------- 256-thread group GEMM micro-kernel (4x4 via 8 FFMA2) ----------------
__device__ __forceinline__ void mma16(const float (*As)[68], const float (*Bs)[68],
                                      int ty, int tx, ull acc[4][2]) {
#pragma unroll
    for (int kk = 0; kk < 16; kk++) {
        float4 av = *(const float4*)&As[kk][ty * 4];
        ulonglong2 bv = *(const ulonglong2*)&Bs[kk][tx * 4];
        ull a0 = pack2(av.x), a1 = pack2(av.y), a2 = pack2(av.z), a3 = pack2(av.w);
        fma2(acc[0][0], a0, bv.x); fma2(acc[0][1], a0, bv.y);
        fma2(acc[1][0], a1, bv.x); fma2(acc[1][1], a1, bv.y);
        fma2(acc[2][0], a2, bv.x); fma2(acc[2][1], a2, bv.y);
        fma2(acc[3][0], a3, bv.x); fma2(acc[3][1], a3, bv.y);
    }
}

// NT: P[m, n0+n] = sum_k A[m,k] * Bm[n0+n, k], m in [0,64), 64-wide n tile.
__device__ __forceinline__ void group_nt(const float* __restrict__ A, int lda,
                                         const float* __restrict__ Bm, int ldb,
                                         float* __restrict__ P, int ldp,
                                         int Nn, int n0, int k0, int klen,
                                         float (*As)[68], float (*Bs)[68],
                                         int gt, int barid) {
    const int tx = gt & 15, ty = gt >> 4;
    const int lr = gt >> 2, lkq = (gt & 3) * 4;
    const int brow = n0 + lr;
    const bool bv = brow < Nn;
    const float* arow = A + (size_t)lr * lda;
    const float* brp  = Bm + (size_t)brow * ldb;
    ull acc[4][2];
#pragma unroll
    for (int i = 0; i < 4; i++) { acc[i][0] = 0ull; acc[i][1] = 0ull; }

    for (int kb = k0; kb < k0 + klen; kb += 16) {
        float4 a = *(const float4*)&arow[kb + lkq];
        float4 b = bv ? *(const float4*)&brp[kb + lkq] : make_float4(0.f, 0.f, 0.f, 0.f);
        As[lkq + 0][lr] = a.x; As[lkq + 1][lr] = a.y; As[lkq + 2][lr] = a.z; As[lkq + 3][lr] = a.w;
        Bs[lkq + 0][lr] = b.x; Bs[lkq + 1][lr] = b.y; Bs[lkq + 2][lr] = b.z; Bs[lkq + 3][lr] = b.w;
        gbar(barid);
        mma16(As, Bs, ty, tx, acc);
        gbar(barid);
    }
    const int n = n0 + tx * 4;
#pragma unroll
    for (int i = 0; i < 4; i++)
        *(ulonglong2*)&P[(size_t)(ty * 4 + i) * ldp + n] = make_ulonglong2(acc[i][0], acc[i][1]);
}

// NN: P[m, n0+n] = sum_k A[m,k] * Bm[k, n0+n]  (A = g_vm, 64 x CP; Bm k-rows guarded < C_)
__device__ __forceinline__ void group_nn(const float* __restrict__ A, int lda,
                                         const float* __restrict__ Bm, int ldb,
                                         float* __restrict__ P, int ldp,
                                         int n0, int k0, int klen,
                                         float (*As)[68], float (*Bs)[68],
                                         int gt, int barid) {
    const int tx = gt & 15, ty = gt >> 4;
    const int lr = gt >> 2, lkq = (gt & 3) * 4;
    const int bk = gt >> 4, bn = (gt & 15) * 4;
    const float* arow = A + (size_t)lr * lda;
    ull acc[4][2];
#pragma unroll
    for (int i = 0; i < 4; i++) { acc[i][0] = 0ull; acc[i][1] = 0ull; }

    for (int kb = k0; kb < k0 + klen; kb += 16) {
        float4 a = *(const float4*)&arow[kb + lkq];
        int krow = kb + bk;
        float4 b = (krow < C_) ? *(const float4*)&Bm[(size_t)krow * ldb + n0 + bn]
                               : make_float4(0.f, 0.f, 0.f, 0.f);
        As[lkq + 0][lr] = a.x; As[lkq + 1][lr] = a.y; As[lkq + 2][lr] = a.z; As[lkq + 3][lr] = a.w;
        *(float4*)&Bs[bk][bn] = b;
        gbar(barid);
        mma16(As, Bs, ty, tx, acc);
        gbar(barid);
    }
    const int n = n0 + tx * 4;
#pragma unroll
    for (int i = 0; i < 4; i++)
        *(ulonglong2*)&P[(size_t)(ty * 4 + i) * ldp + n] = make_ulonglong2(acc[i][0], acc[i][1]);
}

// ---------------- the single fused persistent kernel ----------------
__global__ void __launch_bounds__(1024, 1)
fused_all(const float* __restrict__ x,
          const float* __restrict__ centroids,
          const float* __restrict__ W_hall,
          const float* __restrict__ b_hall,
          const float* __restrict__ W_sel,
          const float* __restrict__ b_sel,
          const float* __restrict__ W_cos,
          float* __restrict__ out, int writeFeat) {
    __shared__ __align__(16) union {
        struct { float As[4][16][68]; float Bs[4][16][68]; } t;   // 34816 B
        float red[64];
    } sm;
    const int tid = threadIdx.x, bid = blockIdx.x;
    const int gid = tid >> 8, gt = tid & 255, barid = gid + 1;
    float (*As)[68] = sm.t.As[gid];
    float (*Bs)[68] = sm.t.Bs[gid];

    // ===== S0a: row norms (one row per warp) =====
    {
        const int gw = bid * 32 + (tid >> 5);
        const int lane = tid & 31;
        if (gw < 2064) {
            const float* src; int mode, idx;
            if (gw < 1000)      { src = centroids + (size_t)gw * F_;          mode = 0; idx = gw; }
            else if (gw < 2000) { src = W_cos + (size_t)(gw - 1000) * F_;     mode = 1; idx = gw - 1000; }
            else                { src = x + (size_t)(gw - 2000) * F_;         mode = 2; idx = gw - 2000; }
            const float4* s4 = (const float4*)src;
            float s = 0.f;
            for (int i = lane; i < F_ / 4; i += 32) {
                float4 v = s4[i];
                s += v.x * v.x + v.y * v.y + v.z * v.z + v.w * v.w;
            }
#pragma unroll
            for (int o = 16; o; o >>= 1) s += __shfl_xor_sync(0xffffffffu, s, o);
            if (lane == 0) {
                if (mode == 0)      g_cn2[idx] = s;
                else if (mode == 1) g_wn[idx]  = sqrtf(s);
                else                g_xn2[idx] = s;
            }
        }
    }

    // ===== S0b: mega GEMMs x @ [centroids; W_hall; W_sel]^T  (1024 items) =====
    for (int item = bid * 4 + gid; item < 1024; item += NB * 4) {
        const int t = item & 63, ks = item >> 6;
        const float* Bm; float* P; int Nn, n0, ldp;
        if (t < 16)      { Bm = centroids; P = g_p_dot[ks];  Nn = C_; n0 = t * 64;        ldp = CP; }
        else if (t < 32) { Bm = W_hall;    P = g_p_hall[ks]; Nn = C_; n0 = (t - 16) * 64; ldp = CP; }
        else             { Bm = W_sel;     P = g_p_sel[ks];  Nn = F_; n0 = (t - 32) * 64; ldp = F_; }
        group_nt(x, F_, Bm, F_, P, ldp, Nn, n0, ks * 128, 128, As, Bs, gt, barid);
    }
    grid_sync(0);

    // ===== S1: reduce dot/hall partials, min-dist, softmax, reachability (64 blocks) =====
    if (bid < B_) {
        const int b = bid, c = tid;
        const bool val = c < C_;
        float hv = -1e30f, d2 = 1e30f;
        if (val) {
            float dot = 0.f, h = 0.f;
#pragma unroll
            for (int s = 0; s < 16; s++) {
                dot += g_p_dot[s][b * CP + c];
                h   += g_p_hall[s][b * CP + c];
            }
            hv = h + b_hall[c];
            d2 = g_xn2[b] + g_cn2[c] - 2.f * dot;
        }
        float md2 = blk_min(d2, sm.red);
        float mh  = blk_max(hv, sm.red);
        float e   = val ? __expf(hv - mh) : 0.f;
        float se  = blk_sum(e, sm.red);
        g_vm[b * CP + c] = e / se;     // c >= C_ writes 0 -> pad for mem gemm
        if (tid == 0) g_reach[b] = 10.f / sqrtf(fmaxf(md2, 1e-30f));
    }
    grid_sync(1);

    // ===== S2: memory_feature = vm @ centroids  (512 items, k over padded CP) =====
    for (int item = bid * 4 + gid; item < 512; item += NB * 4) {
        const int nt = item & 31, ks = item >> 5;
        group_nn(g_vm, CP, centroids, F_, g_p_mem[ks], F_, nt * 64, ks * 64, 64,
                 As, Bs, gt, barid);
    }
    grid_sync(2);

    // ===== S3: feat = reach*(x + tanh(sel)*mem), outputs, row norm (64 blocks) =====
    if (bid < B_) {
        const int b = bid;
        const float reach = g_reach[b];
        float n2 = 0.f;
#pragma unroll
        for (int f = tid; f < F_; f += 1024) {
            float mem = 0.f, sz = 0.f;
#pragma unroll
            for (int s = 0; s < 16; s++) mem += g_p_mem[s][b * F_ + f];
#pragma unroll
            for (int s = 0; s < 16; s++) sz  += g_p_sel[s][b * F_ + f];
            float sel  = tanhf(sz + b_sel[f]);
            float xv   = x[(size_t)b * F_ + f];
            float inf  = sel * mem;
            float feat = reach * (xv + inf);
            g_feat[b * F_ + f] = feat;
            n2 += feat * feat;
            if (writeFeat) {
                out[64000 + b * F_ + f]  = xv;   // direct_feature
                out[195072 + b * F_ + f] = inf;  // infused_feature
            }
        }
        float tot = blk_sum(n2, sm.red);
        if (tid == 0) g_scale[b] = 16.f / (1.f + sqrtf(tot));
    }
    grid_sync(3);

    // ===== S4: cos logits GEMM feat @ W_cos^T  (512 items) =====
    for (int item = bid * 4 + gid; item < 512; item += NB * 4) {
        const int nt = item & 15, ks = item >> 4;
        group_nt(g_feat, F_, W_cos, F_, g_p_cos[ks], CP, C_, nt * 64, ks * 64, 64,
                 As, Bs, gt, barid);
    }
    grid_sync(4);

    // ===== S5: final scaled logits =====
    {
        const int i = bid * 1024 + tid;
        if (i < B_ * C_) {
            const int b = i / C_, c = i - b * C_;
            float s = 0.f;
#pragma unroll
            for (int ss = 0; ss < 32; ss++) s += g_p_cos[ss][b * CP + c];
            out[i] = s * g_scale[b] / g_wn[c];
        }
    }
}

// ================= launch =================
extern "C" void kernel_launch(void* const* d_in, const int* in_sizes, int n_in,
                              void* d_out, int out_size) {
    const float* x         = (const float*)d_in[0];
    const float* centroids = (const float*)d_in[1];
    const float* W_hall    = (const float*)d_in[2];
    const float* b_hall    = (const float*)d_in[3];
    const float* W_sel     = (const float*)d_in[4];
    const float* b_sel     = (const float*)d_in[5];
    const float* W_cos     = (const float*)d_in[6];
    float* out = (float*)d_out;

    int writeFeat = (out_size >= 326144) ? 1 : 0;
    fused_all<<<NB, 1024>>>(x, centroids, W_hall, b_hall, W_sel, b_sel, W_cos,
                            out, writeFeat);
}

// round 7
// speedup vs baseline: 1.6675x; 1.0004x over previous
#include <cuda_runtime.h>
#include <math.h>
#include <stdint.h>

#define B_   64
#define C_   1000
#define F_   2048
#define CP   1024
#define NB   148
#define KSA  8
#define KSM  16
#define KSC  32
typedef unsigned long long ull;

// ---------------- scratch (static __device__, no allocations) ----------------
__device__ __align__(256) float g_p_dot[KSA][B_ * CP];
__device__ __align__(256) float g_p_hall[KSA][B_ * CP];
__device__ __align__(256) float g_p_sel[KSA][B_ * F_];
__device__ __align__(256) float g_p_mem[KSM][B_ * F_];
__device__ __align__(256) float g_p_cos[KSC][B_ * CP];
__device__ __align__(256) float g_vm[B_ * CP];
__device__ __align__(256) float g_feat[B_ * F_];
__device__ float g_cn2[CP];
__device__ float g_wn[CP];
__device__ float g_xn2[B_];
__device__ float g_reach[B_];
__device__ float g_scale[B_];
__device__ unsigned int g_arr[8];
__device__ unsigned int g_flag[8];

// ---------------- f32x2 helpers ----------------
__device__ __forceinline__ ull pack2(float v) {
    ull r;
    asm("mov.b64 %0, {%1, %1};" : "=l"(r) : "f"(v));
    return r;
}
__device__ __forceinline__ void fma2(ull& d, ull a, ull b) {
    asm("fma.rn.f32x2 %0, %1, %2, %0;" : "+l"(d) : "l"(a), "l"(b));
}

// ---------------- group barrier (256-thread group, named barrier) ----------------
__device__ __forceinline__ void gbar(int id) {
    asm volatile("bar.sync %0, 256;" :: "r"(id) : "memory");
}

// ---------------- grid sync (all NB blocks resident; graph-replay-safe) ----------------
__device__ __forceinline__ void grid_sync(int s) {
    __threadfence();
    __syncthreads();
    if (threadIdx.x == 0) {
        unsigned int before = atomicOr(&g_flag[s], 0u);
        unsigned int old = atomicAdd(&g_arr[s], 1u);
        if (old == NB - 1) {
            g_arr[s] = 0;
            __threadfence();
            atomicAdd(&g_flag[s], 1u);
        } else {
            while (atomicOr(&g_flag[s], 0u) == before) __nanosleep(64);
        }
    }
    __syncthreads();
    __threadfence();
}

// ---------------- block reductions (1024 threads, two-level) ----------------
__device__ __forceinline__ float blk_sum(float v, float* red) {
#pragma unroll
    for (int o = 16; o; o >>= 1) v += __shfl_xor_sync(0xffffffffu, v, o);
    if ((threadIdx.x & 31) == 0) red[threadIdx.x >> 5] = v;
    __syncthreads();
    if (threadIdx.x < 32) {
        float s = red[threadIdx.x];
#pragma unroll
        for (int o = 16; o; o >>= 1) s += __shfl_xor_sync(0xffffffffu, s, o);
        if (threadIdx.x == 0) red[0] = s;
    }
    __syncthreads();
    float r = red[0];
    __syncthreads();
    return r;
}
__device__ __forceinline__ float blk_min(float v, float* red) {
#pragma unroll
    for (int o = 16; o; o >>= 1) v = fminf(v, __shfl_xor_sync(0xffffffffu, v, o));
    if ((threadIdx.x & 31) == 0) red[threadIdx.x >> 5] = v;
    __syncthreads();
    if (threadIdx.x < 32) {
        float s = red[threadIdx.x];
#pragma unroll
        for (int o = 16; o; o >>= 1) s = fminf(s, __shfl_xor_sync(0xffffffffu, s, o));
        if (threadIdx.x == 0) red[0] = s;
    }
    __syncthreads();
    float r = red[0];
    __syncthreads();
    return r;
}
__device__ __forceinline__ float blk_max(float v, float* red) {
#pragma unroll
    for (int o = 16; o; o >>= 1) v = fmaxf(v, __shfl_xor_sync(0xffffffffu, v, o));
    if ((threadIdx.x & 31) == 0) red[threadIdx.x >> 5] = v;
    __syncthreads();
    if (threadIdx.x < 32) {
        float s = red[threadIdx.x];
#pragma unroll
        for (int o = 16; o; o >>= 1) s = fmaxf(s, __shfl_xor_sync(0xffffffffu, s, o));
        if (threadIdx.x == 0) red[0] = s;
    }
    __syncthreads();
    float r = red[0];
    __syncthreads();
    return r;
}

// ---------------- 256-thread group GEMM micro-kernel (4x4 via 8 FFMA2) ----------------
__device__ __forceinline__ void mma16(const float (*As)[68], const float (*Bs)[68],
                                      int ty, int tx, ull acc[4][2]) {
#pragma unroll
    for (int kk = 0; kk < 16; kk++) {
        float4 av = *(const float4*)&As[kk][ty * 4];
        ulonglong2 bv = *(const ulonglong2*)&Bs[kk][tx * 4];
        ull a0 = pack2(av.x), a1 = pack2(av.y), a2 = pack2(av.z), a3 = pack2(av.w);
        fma2(acc[0][0], a0, bv.x); fma2(acc[0][1], a0, bv.y);
        fma2(acc[1][0], a1, bv.x); fma2(acc[1][1], a1, bv.y);
        fma2(acc[2][0], a2, bv.x); fma2(acc[2][1], a2, bv.y);
        fma2(acc[3][0], a3, bv.x); fma2(acc[3][1], a3, bv.y);
    }
}

#define TILE_F (16 * 68)   // floats per As or Bs buffer

// NT: P[m, n0+n] = sum_k A[m,k] * Bm[n0+n, k]; double-buffered, reg-prefetch.
__device__ __forceinline__ void group_nt(const float* __restrict__ A, int lda,
                                         const float* __restrict__ Bm, int ldb,
                                         float* __restrict__ P, int ldp,
                                         int Nn, int n0, int k0, int klen,
                                         float* gsm, int gt, int barid) {
    const int tx = gt & 15, ty = gt >> 4;
    const int lr = gt >> 2, lkq = (gt & 3) * 4;
    const int brow = n0 + lr;
    const bool bv = brow < Nn;
    const float* arow = A + (size_t)lr * lda;
    const float* brp  = Bm + (size_t)brow * ldb;
    float (*As0)[68] = (float(*)[68])(gsm);
    float (*Bs0)[68] = (float(*)[68])(gsm + TILE_F);
    float (*As1)[68] = (float(*)[68])(gsm + 2 * TILE_F);
    float (*Bs1)[68] = (float(*)[68])(gsm + 3 * TILE_F);
    ull acc[4][2];
#pragma unroll
    for (int i = 0; i < 4; i++) { acc[i][0] = 0ull; acc[i][1] = 0ull; }

    const int nt = klen >> 4;
    float4 a = *(const float4*)&arow[k0 + lkq];
    float4 b = bv ? *(const float4*)&brp[k0 + lkq] : make_float4(0.f, 0.f, 0.f, 0.f);
    As0[lkq + 0][lr] = a.x; As0[lkq + 1][lr] = a.y; As0[lkq + 2][lr] = a.z; As0[lkq + 3][lr] = a.w;
    Bs0[lkq + 0][lr] = b.x; Bs0[lkq + 1][lr] = b.y; Bs0[lkq + 2][lr] = b.z; Bs0[lkq + 3][lr] = b.w;
    gbar(barid);

    for (int i = 0; i < nt; i++) {
        const bool hn = (i + 1) < nt;
        float4 na, nb;
        if (hn) {
            const int kn = k0 + (i + 1) * 16;
            na = *(const float4*)&arow[kn + lkq];
            nb = bv ? *(const float4*)&brp[kn + lkq] : make_float4(0.f, 0.f, 0.f, 0.f);
        }
        if (i & 1) mma16(As1, Bs1, ty, tx, acc);
        else       mma16(As0, Bs0, ty, tx, acc);
        if (hn) {
            float (*Ad)[68] = (i & 1) ? As0 : As1;
            float (*Bd)[68] = (i & 1) ? Bs0 : Bs1;
            Ad[lkq + 0][lr] = na.x; Ad[lkq + 1][lr] = na.y; Ad[lkq + 2][lr] = na.z; Ad[lkq + 3][lr] = na.w;
            Bd[lkq + 0][lr] = nb.x; Bd[lkq + 1][lr] = nb.y; Bd[lkq + 2][lr] = nb.z; Bd[lkq + 3][lr] = nb.w;
        }
        gbar(barid);
    }
    const int n = n0 + tx * 4;
#pragma unroll
    for (int i = 0; i < 4; i++)
        *(ulonglong2*)&P[(size_t)(ty * 4 + i) * ldp + n] = make_ulonglong2(acc[i][0], acc[i][1]);
}

// NN: P[m, n0+n] = sum_k A[m,k] * Bm[k, n0+n]  (A padded; Bm k-rows guarded < C_)
__device__ __forceinline__ void group_nn(const float* __restrict__ A, int lda,
                                         const float* __restrict__ Bm, int ldb,
                                         float* __restrict__ P, int ldp,
                                         int n0, int k0, int klen,
                                         float* gsm, int gt, int barid) {
    const int tx = gt & 15, ty = gt >> 4;
    const int lr = gt >> 2, lkq = (gt & 3) * 4;
    const int bk = gt >> 4, bn = (gt & 15) * 4;
    const float* arow = A + (size_t)lr * lda;
    float (*As0)[68] = (float(*)[68])(gsm);
    float (*Bs0)[68] = (float(*)[68])(gsm + TILE_F);
    float (*As1)[68] = (float(*)[68])(gsm + 2 * TILE_F);
    float (*Bs1)[68] = (float(*)[68])(gsm + 3 * TILE_F);
    ull acc[4][2];
#pragma unroll
    for (int i = 0; i < 4; i++) { acc[i][0] = 0ull; acc[i][1] = 0ull; }

    const int nt = klen >> 4;
    {
        float4 a = *(const float4*)&arow[k0 + lkq];
        int krow = k0 + bk;
        float4 b = (krow < C_) ? *(const float4*)&Bm[(size_t)krow * ldb + n0 + bn]
                               : make_float4(0.f, 0.f, 0.f, 0.f);
        As0[lkq + 0][lr] = a.x; As0[lkq + 1][lr] = a.y; As0[lkq + 2][lr] = a.z; As0[lkq + 3][lr] = a.w;
        *(float4*)&Bs0[bk][bn] = b;
    }
    gbar(barid);

    for (int i = 0; i < nt; i++) {
        const bool hn = (i + 1) < nt;
        float4 na, nb;
        if (hn) {
            const int kn = k0 + (i + 1) * 16;
            na = *(const float4*)&arow[kn + lkq];
            int krow = kn + bk;
            nb = (krow < C_) ? *(const float4*)&Bm[(size_t)krow * ldb + n0 + bn]
                             : make_float4(0.f, 0.f, 0.f, 0.f);
        }
        if (i & 1) mma16(As1, Bs1, ty, tx, acc);
        else       mma16(As0, Bs0, ty, tx, acc);
        if (hn) {
            float (*Ad)[68] = (i & 1) ? As0 : As1;
            float (*Bd)[68] = (i & 1) ? Bs0 : Bs1;
            Ad[lkq + 0][lr] = na.x; Ad[lkq + 1][lr] = na.y; Ad[lkq + 2][lr] = na.z; Ad[lkq + 3][lr] = na.w;
            *(float4*)&Bd[bk][bn] = nb;
        }
        gbar(barid);
    }
    const int n = n0 + tx * 4;
#pragma unroll
    for (int i = 0; i < 4; i++)
        *(ulonglong2*)&P[(size_t)(ty * 4 + i) * ldp + n] = make_ulonglong2(acc[i][0], acc[i][1]);
}

// ---------------- the single fused persistent kernel ----------------
__global__ void __launch_bounds__(1024, 1)
fused_all(const float* __restrict__ x,
          const float* __restrict__ centroids,
          const float* __restrict__ W_hall,
          const float* __restrict__ b_hall,
          const float* __restrict__ W_sel,
          const float* __restrict__ b_sel,
          const float* __restrict__ W_cos,
          float* __restrict__ out, int writeFeat) {
    extern __shared__ __align__(16) float dsm[];   // 4 groups * 4 buffers * TILE_F
    __shared__ float red[32];
    const int tid = threadIdx.x, bid = blockIdx.x;
    const int gid = tid >> 8, gt = tid & 255, barid = gid + 1;
    float* gsm = dsm + gid * 4 * TILE_F;

    // ===== S0a: row norms (one row per warp) =====
    {
        const int gw = bid * 32 + (tid >> 5);
        const int lane = tid & 31;
        if (gw < 2064) {
            const float* src; int mode, idx;
            if (gw < 1000)      { src = centroids + (size_t)gw * F_;      mode = 0; idx = gw; }
            else if (gw < 2000) { src = W_cos + (size_t)(gw - 1000) * F_; mode = 1; idx = gw - 1000; }
            else                { src = x + (size_t)(gw - 2000) * F_;     mode = 2; idx = gw - 2000; }
            const float4* s4 = (const float4*)src;
            float s = 0.f;
            for (int i = lane; i < F_ / 4; i += 32) {
                float4 v = s4[i];
                s += v.x * v.x + v.y * v.y + v.z * v.z + v.w * v.w;
            }
#pragma unroll
            for (int o = 16; o; o >>= 1) s += __shfl_xor_sync(0xffffffffu, s, o);
            if (lane == 0) {
                if (mode == 0)      g_cn2[idx] = s;
                else if (mode == 1) g_wn[idx]  = sqrtf(s);
                else                g_xn2[idx] = s;
            }
        }
    }

    // ===== S0b: mega GEMMs x @ [centroids; W_hall; W_sel]^T  (512 items, klen 256) =====
    for (int item = bid * 4 + gid; item < 64 * KSA; item += NB * 4) {
        const int t = item & 63, ks = item >> 6;
        const float* Bm; float* P; int Nn, n0, ldp;
        if (t < 16)      { Bm = centroids; P = g_p_dot[ks];  Nn = C_; n0 = t * 64;        ldp = CP; }
        else if (t < 32) { Bm = W_hall;    P = g_p_hall[ks]; Nn = C_; n0 = (t - 16) * 64; ldp = CP; }
        else             { Bm = W_sel;     P = g_p_sel[ks];  Nn = F_; n0 = (t - 32) * 64; ldp = F_; }
        group_nt(x, F_, Bm, F_, P, ldp, Nn, n0, ks * 256, 256, gsm, gt, barid);
    }
    grid_sync(0);

    // ===== S1: reduce dot/hall partials, min-dist, softmax, reachability (64 blocks) =====
    if (bid < B_) {
        const int b = bid, c = tid;
        const bool val = c < C_;
        float hv = -1e30f, d2 = 1e30f;
        if (val) {
            float dot = 0.f, h = 0.f;
#pragma unroll
            for (int s = 0; s < KSA; s++) {
                dot += g_p_dot[s][b * CP + c];
                h   += g_p_hall[s][b * CP + c];
            }
            hv = h + b_hall[c];
            d2 = g_xn2[b] + g_cn2[c] - 2.f * dot;
        }
        float md2 = blk_min(d2, red);
        float mh  = blk_max(hv, red);
        float e   = val ? __expf(hv - mh) : 0.f;
        float se  = blk_sum(e, red);
        g_vm[b * CP + c] = e / se;     // c >= C_ writes 0 -> pad for mem gemm
        if (tid == 0) g_reach[b] = 10.f / sqrtf(fmaxf(md2, 1e-30f));
    }
    grid_sync(1);

    // ===== S2: memory_feature = vm @ centroids  (512 items, klen 64 over padded CP) =====
    for (int item = bid * 4 + gid; item < 32 * KSM; item += NB * 4) {
        const int nt = item & 31, ks = item >> 5;
        group_nn(g_vm, CP, centroids, F_, g_p_mem[ks], F_, nt * 64, ks * 64, 64,
                 gsm, gt, barid);
    }
    grid_sync(2);

    // ===== S3: feat = reach*(x + tanh(sel)*mem), outputs, row norm (64 blocks) =====
    if (bid < B_) {
        const int b = bid;
        const float reach = g_reach[b];
        float n2 = 0.f;
#pragma unroll
        for (int f = tid; f < F_; f += 1024) {
            float mem = 0.f, sz = 0.f;
#pragma unroll
            for (int s = 0; s < KSM; s++) mem += g_p_mem[s][b * F_ + f];
#pragma unroll
            for (int s = 0; s < KSA; s++) sz  += g_p_sel[s][b * F_ + f];
            float sel  = tanhf(sz + b_sel[f]);
            float xv   = x[(size_t)b * F_ + f];
            float inf  = sel * mem;
            float feat = reach * (xv + inf);
            g_feat[b * F_ + f] = feat;
            n2 += feat * feat;
            if (writeFeat) {
                out[64000 + b * F_ + f]  = xv;   // direct_feature
                out[195072 + b * F_ + f] = inf;  // infused_feature
            }
        }
        float tot = blk_sum(n2, red);
        if (tid == 0) g_scale[b] = 16.f / (1.f + sqrtf(tot));
    }
    grid_sync(3);

    // ===== S4: cos logits GEMM feat @ W_cos^T  (512 items, klen 64) =====
    for (int item = bid * 4 + gid; item < 16 * KSC; item += NB * 4) {
        const int nt = item & 15, ks = item >> 4;
        group_nt(g_feat, F_, W_cos, F_, g_p_cos[ks], CP, C_, nt * 64, ks * 64, 64,
                 gsm, gt, barid);
    }
    grid_sync(4);

    // ===== S5: final scaled logits =====
    {
        const int i = bid * 1024 + tid;
        if (i < B_ * C_) {
            const int b = i / C_, c = i - b * C_;
            float s = 0.f;
#pragma unroll
            for (int ss = 0; ss < KSC; ss++) s += g_p_cos[ss][b * CP + c];
            out[i] = s * g_scale[b] / g_wn[c];
        }
    }
}

// ================= launch =================
#define DSM_BYTES (4 * 4 * TILE_F * 4)   // 4 groups * 4 buffers * 16*68 floats = 69632 B

extern "C" void kernel_launch(void* const* d_in, const int* in_sizes, int n_in,
                              void* d_out, int out_size) {
    const float* x         = (const float*)d_in[0];
    const float* centroids = (const float*)d_in[1];
    const float* W_hall    = (const float*)d_in[2];
    const float* b_hall    = (const float*)d_in[3];
    const float* W_sel     = (const float*)d_in[4];
    const float* b_sel     = (const float*)d_in[5];
    const float* W_cos     = (const float*)d_in[6];
    float* out = (float*)d_out;

    cudaFuncSetAttribute(fused_all, cudaFuncAttributeMaxDynamicSharedMemorySize, DSM_BYTES);

    int writeFeat = (out_size >= 326144) ? 1 : 0;
    fused_all<<<NB, 1024, DSM_BYTES>>>(x, centroids, W_hall, b_hall, W_sel, b_sel, W_cos,
                                       out, writeFeat);
}

// round 8
// speedup vs baseline: 2.0208x; 1.2119x over previous
#include <cuda_runtime.h>
#include <cuda_bf16.h>
#include <math.h>
#include <stdint.h>

#define B_   64
#define C_   1000
#define F_   2048
#define CP   1024
#define NB   148
#define KSA  8
#define KSM  16
#define KSC  32
typedef unsigned long long ull;

// ---------------- scratch (static __device__, no allocations) ----------------
__device__ __align__(256) float g_p_dot[KSA][B_ * CP];
__device__ __align__(256) float g_p_hall[KSA][B_ * CP];
__device__ __align__(256) float g_p_sel[KSA][B_ * F_];
__device__ __align__(256) float g_p_mem[KSM][B_ * F_];
__device__ __align__(256) float g_p_cos[KSC][B_ * CP];
__device__ __align__(256) float g_vm[B_ * CP];
__device__ __align__(256) float g_feat[B_ * F_];
__device__ float g_cn2[CP];
__device__ float g_wn[CP];
__device__ float g_xn2[B_];
__device__ float g_reach[B_];
__device__ float g_scale[B_];
__device__ unsigned int g_arr[8];
__device__ unsigned int g_flag[8];

// ---------------- group barrier / grid sync ----------------
__device__ __forceinline__ void gbar(int id) {
    asm volatile("bar.sync %0, 256;" :: "r"(id) : "memory");
}
__device__ __forceinline__ void grid_sync(int s) {
    __threadfence();
    __syncthreads();
    if (threadIdx.x == 0) {
        unsigned int before = atomicOr(&g_flag[s], 0u);
        unsigned int old = atomicAdd(&g_arr[s], 1u);
        if (old == NB - 1) {
            g_arr[s] = 0;
            __threadfence();
            atomicAdd(&g_flag[s], 1u);
        } else {
            while (atomicOr(&g_flag[s], 0u) == before) __nanosleep(64);
        }
    }
    __syncthreads();
    __threadfence();
}

// ---------------- block reductions (1024 threads) ----------------
__device__ __forceinline__ float blk_sum(float v, float* red) {
#pragma unroll
    for (int o = 16; o; o >>= 1) v += __shfl_xor_sync(0xffffffffu, v, o);
    if ((threadIdx.x & 31) == 0) red[threadIdx.x >> 5] = v;
    __syncthreads();
    if (threadIdx.x < 32) {
        float s = red[threadIdx.x];
#pragma unroll
        for (int o = 16; o; o >>= 1) s += __shfl_xor_sync(0xffffffffu, s, o);
        if (threadIdx.x == 0) red[0] = s;
    }
    __syncthreads();
    float r = red[0];
    __syncthreads();
    return r;
}
__device__ __forceinline__ float blk_min(float v, float* red) {
#pragma unroll
    for (int o = 16; o; o >>= 1) v = fminf(v, __shfl_xor_sync(0xffffffffu, v, o));
    if ((threadIdx.x & 31) == 0) red[threadIdx.x >> 5] = v;
    __syncthreads();
    if (threadIdx.x < 32) {
        float s = red[threadIdx.x];
#pragma unroll
        for (int o = 16; o; o >>= 1) s = fminf(s, __shfl_xor_sync(0xffffffffu, s, o));
        if (threadIdx.x == 0) red[0] = s;
    }
    __syncthreads();
    float r = red[0];
    __syncthreads();
    return r;
}
__device__ __forceinline__ float blk_max(float v, float* red) {
#pragma unroll
    for (int o = 16; o; o >>= 1) v = fmaxf(v, __shfl_xor_sync(0xffffffffu, v, o));
    if ((threadIdx.x & 31) == 0) red[threadIdx.x >> 5] = v;
    __syncthreads();
    if (threadIdx.x < 32) {
        float s = red[threadIdx.x];
#pragma unroll
        for (int o = 16; o; o >>= 1) s = fmaxf(s, __shfl_xor_sync(0xffffffffu, s, o));
        if (threadIdx.x == 0) red[0] = s;
    }
    __syncthreads();
    float r = red[0];
    __syncthreads();
    return r;
}

// ---------------- bf16 hi/lo conversion ----------------
__device__ __forceinline__ void cvt_hilo(float4 v, uint2& hi, uint2& lo) {
    uint32_t bx = __float_as_uint(v.x), by = __float_as_uint(v.y);
    uint32_t bz = __float_as_uint(v.z), bw = __float_as_uint(v.w);
    hi.x = __byte_perm(bx, by, 0x7632);
    hi.y = __byte_perm(bz, bw, 0x7632);
    float rx = v.x - __uint_as_float(bx & 0xffff0000u);
    float ry = v.y - __uint_as_float(by & 0xffff0000u);
    float rz = v.z - __uint_as_float(bz & 0xffff0000u);
    float rw = v.w - __uint_as_float(bw & 0xffff0000u);
    asm("cvt.rn.bf16x2.f32 %0, %1, %2;" : "=r"(lo.x) : "f"(ry), "f"(rx));
    asm("cvt.rn.bf16x2.f32 %0, %1, %2;" : "=r"(lo.y) : "f"(rw), "f"(rz));
}
__device__ __forceinline__ void cvt_hilo1(float v, __nv_bfloat16& h, __nv_bfloat16& l) {
    uint32_t b = __float_as_uint(v);
    unsigned short hs = (unsigned short)(b >> 16);
    h = *(__nv_bfloat16*)&hs;
    float r = v - __uint_as_float(b & 0xffff0000u);
    l = __float2bfloat16_rn(r);
}

__device__ __forceinline__ void mma16816(float* d,
                                         uint32_t a0, uint32_t a1, uint32_t a2, uint32_t a3,
                                         uint32_t b0, uint32_t b1) {
    asm volatile("mma.sync.aligned.m16n8k16.row.col.f32.bf16.bf16.f32 "
        "{%0,%1,%2,%3}, {%4,%5,%6,%7}, {%8,%9}, {%0,%1,%2,%3};"
        : "+f"(d[0]), "+f"(d[1]), "+f"(d[2]), "+f"(d[3])
        : "r"(a0), "r"(a1), "r"(a2), "r"(a3), "r"(b0), "r"(b1));
}

#define GSM_F (64 * 72)   // bf16 elements per tile array

// ---------------- HMMA mma phase over one 64x64 hi/lo tile pair ----------------
__device__ __forceinline__ void tile_hmma(__nv_bfloat16 (*Ah)[72], __nv_bfloat16 (*Al)[72],
                                          __nv_bfloat16 (*Bh)[72], __nv_bfloat16 (*Bl)[72],
                                          int m0, int nh, int fr, int fc, float acc[4][4]) {
#pragma unroll
    for (int kk = 0; kk < 4; kk++) {
        const int kc = kk * 16 + fc;
        uint32_t ah0 = *(const uint32_t*)&Ah[m0 + fr][kc];
        uint32_t ah1 = *(const uint32_t*)&Ah[m0 + fr + 8][kc];
        uint32_t ah2 = *(const uint32_t*)&Ah[m0 + fr][kc + 8];
        uint32_t ah3 = *(const uint32_t*)&Ah[m0 + fr + 8][kc + 8];
        uint32_t al0 = *(const uint32_t*)&Al[m0 + fr][kc];
        uint32_t al1 = *(const uint32_t*)&Al[m0 + fr + 8][kc];
        uint32_t al2 = *(const uint32_t*)&Al[m0 + fr][kc + 8];
        uint32_t al3 = *(const uint32_t*)&Al[m0 + fr + 8][kc + 8];
#pragma unroll
        for (int nt = 0; nt < 4; nt++) {
            const int bn = nh + nt * 8 + fr;
            uint32_t bh0 = *(const uint32_t*)&Bh[bn][kc];
            uint32_t bh1 = *(const uint32_t*)&Bh[bn][kc + 8];
            uint32_t bl0 = *(const uint32_t*)&Bl[bn][kc];
            uint32_t bl1 = *(const uint32_t*)&Bl[bn][kc + 8];
            mma16816(acc[nt], ah0, ah1, ah2, ah3, bh0, bh1);
            mma16816(acc[nt], ah0, ah1, ah2, ah3, bl0, bl1);
            mma16816(acc[nt], al0, al1, al2, al3, bh0, bh1);
        }
    }
}

// NT: P[m, n0+n] = sum_k A[m,k] * Bm[n0+n, k]; hi/lo HMMA; klen % 64 == 0.
// P must be padded so unguarded column stores are safe (CP / F_ strides).
__device__ __forceinline__ void group_nt_hmma(const float* __restrict__ A, int lda,
                                              const float* __restrict__ Bm, int ldb,
                                              float* __restrict__ P, int ldp,
                                              int Nn, int n0, int k0, int klen,
                                              __nv_bfloat16* gsm, int gt, int barid) {
    __nv_bfloat16 (*Ah)[72] = (__nv_bfloat16(*)[72])(gsm);
    __nv_bfloat16 (*Al)[72] = (__nv_bfloat16(*)[72])(gsm + GSM_F);
    __nv_bfloat16 (*Bh)[72] = (__nv_bfloat16(*)[72])(gsm + 2 * GSM_F);
    __nv_bfloat16 (*Bl)[72] = (__nv_bfloat16(*)[72])(gsm + 3 * GSM_F);
    const int lane = gt & 31, wg = gt >> 5;
    const int m0 = (wg & 3) * 16, nh = (wg >> 2) * 32;
    const int fr = lane >> 2, fc = (lane & 3) * 2;
    const int row = gt >> 2, kq = (gt & 3) * 16;
    const bool bv = (n0 + row) < Nn;

    float acc[4][4];
#pragma unroll
    for (int i = 0; i < 4; i++)
#pragma unroll
        for (int j = 0; j < 4; j++) acc[i][j] = 0.f;

    for (int kb = k0; kb < k0 + klen; kb += 64) {
        const float4* ap = (const float4*)(A + (size_t)row * lda + kb + kq);
        const float4* bp = (const float4*)(Bm + (size_t)(n0 + row) * ldb + kb + kq);
#pragma unroll
        for (int i = 0; i < 4; i++) {
            uint2 h, l;
            cvt_hilo(ap[i], h, l);
            *(uint2*)&Ah[row][kq + i * 4] = h;
            *(uint2*)&Al[row][kq + i * 4] = l;
            float4 v = bv ? bp[i] : make_float4(0.f, 0.f, 0.f, 0.f);
            cvt_hilo(v, h, l);
            *(uint2*)&Bh[row][kq + i * 4] = h;
            *(uint2*)&Bl[row][kq + i * 4] = l;
        }
        gbar(barid);
        tile_hmma(Ah, Al, Bh, Bl, m0, nh, fr, fc, acc);
        gbar(barid);
    }
#pragma unroll
    for (int nt = 0; nt < 4; nt++) {
        const int n = n0 + nh + nt * 8 + fc;
        *(float2*)&P[(size_t)(m0 + fr) * ldp + n]     = make_float2(acc[nt][0], acc[nt][1]);
        *(float2*)&P[(size_t)(m0 + fr + 8) * ldp + n] = make_float2(acc[nt][2], acc[nt][3]);
    }
}

// NN: P[m, n0+n] = sum_k A[m,k] * Bm[k, n0+n]; Bm k-rows guarded < C_; klen == 64.
__device__ __forceinline__ void group_nn_hmma(const float* __restrict__ A, int lda,
                                              const float* __restrict__ Bm, int ldb,
                                              float* __restrict__ P, int ldp,
                                              int n0, int k0,
                                              __nv_bfloat16* gsm, int gt, int barid) {
    __nv_bfloat16 (*Ah)[72] = (__nv_bfloat16(*)[72])(gsm);
    __nv_bfloat16 (*Al)[72] = (__nv_bfloat16(*)[72])(gsm + GSM_F);
    __nv_bfloat16 (*Bh)[72] = (__nv_bfloat16(*)[72])(gsm + 2 * GSM_F);
    __nv_bfloat16 (*Bl)[72] = (__nv_bfloat16(*)[72])(gsm + 3 * GSM_F);
    const int lane = gt & 31, wg = gt >> 5;
    const int m0 = (wg & 3) * 16, nh = (wg >> 2) * 32;
    const int fr = lane >> 2, fc = (lane & 3) * 2;
    const int row = gt >> 2, kq = (gt & 3) * 16;

    float acc[4][4];
#pragma unroll
    for (int i = 0; i < 4; i++)
#pragma unroll
        for (int j = 0; j < 4; j++) acc[i][j] = 0.f;

    // A (vm) 64x64 fp32 -> hi/lo
    {
        const float4* ap = (const float4*)(A + (size_t)row * lda + k0 + kq);
#pragma unroll
        for (int i = 0; i < 4; i++) {
            uint2 h, l;
            cvt_hilo(ap[i], h, l);
            *(uint2*)&Ah[row][kq + i * 4] = h;
            *(uint2*)&Al[row][kq + i * 4] = l;
        }
    }
    // B (centroids) 64k x 64n -> hi/lo transposed into [n][k]
    {
        const int nq = (gt & 15) * 4;
#pragma unroll
        for (int it = 0; it < 4; it++) {
            const int krl = (gt >> 4) + it * 16;
            const int krow = k0 + krl;
            float4 v = (krow < C_) ? *(const float4*)(Bm + (size_t)krow * ldb + n0 + nq)
                                   : make_float4(0.f, 0.f, 0.f, 0.f);
            __nv_bfloat16 h0, l0, h1, l1, h2, l2, h3, l3;
            cvt_hilo1(v.x, h0, l0); cvt_hilo1(v.y, h1, l1);
            cvt_hilo1(v.z, h2, l2); cvt_hilo1(v.w, h3, l3);
            Bh[nq + 0][krl] = h0; Bl[nq + 0][krl] = l0;
            Bh[nq + 1][krl] = h1; Bl[nq + 1][krl] = l1;
            Bh[nq + 2][krl] = h2; Bl[nq + 2][krl] = l2;
            Bh[nq + 3][krl] = h3; Bl[nq + 3][krl] = l3;
        }
    }
    gbar(barid);
    tile_hmma(Ah, Al, Bh, Bl, m0, nh, fr, fc, acc);
    gbar(barid);
#pragma unroll
    for (int nt = 0; nt < 4; nt++) {
        const int n = n0 + nh + nt * 8 + fc;
        *(float2*)&P[(size_t)(m0 + fr) * ldp + n]     = make_float2(acc[nt][0], acc[nt][1]);
        *(float2*)&P[(size_t)(m0 + fr + 8) * ldp + n] = make_float2(acc[nt][2], acc[nt][3]);
    }
}

// ---------------- the single fused persistent kernel ----------------
__global__ void __launch_bounds__(1024, 1)
fused_all(const float* __restrict__ x,
          const float* __restrict__ centroids,
          const float* __restrict__ W_hall,
          const float* __restrict__ b_hall,
          const float* __restrict__ W_sel,
          const float* __restrict__ b_sel,
          const float* __restrict__ W_cos,
          float* __restrict__ out, int writeFeat) {
    extern __shared__ __align__(16) __nv_bfloat16 dsm[];   // 4 groups * 4 * GSM_F
    __shared__ float red[32];
    const int tid = threadIdx.x, bid = blockIdx.x;
    const int gid = tid >> 8, gt = tid & 255, barid = gid + 1;
    __nv_bfloat16* gsm = dsm + gid * 4 * GSM_F;

    // ===== S0a: row norms (one row per warp) =====
    {
        const int gw = bid * 32 + (tid >> 5);
        const int lane = tid & 31;
        if (gw < 2064) {
            const float* src; int mode, idx;
            if (gw < 1000)      { src = centroids + (size_t)gw * F_;      mode = 0; idx = gw; }
            else if (gw < 2000) { src = W_cos + (size_t)(gw - 1000) * F_; mode = 1; idx = gw - 1000; }
            else                { src = x + (size_t)(gw - 2000) * F_;     mode = 2; idx = gw - 2000; }
            const float4* s4 = (const float4*)src;
            float s = 0.f;
            for (int i = lane; i < F_ / 4; i += 32) {
                float4 v = s4[i];
                s += v.x * v.x + v.y * v.y + v.z * v.z + v.w * v.w;
            }
#pragma unroll
            for (int o = 16; o; o >>= 1) s += __shfl_xor_sync(0xffffffffu, s, o);
            if (lane == 0) {
                if (mode == 0)      g_cn2[idx] = s;
                else if (mode == 1) g_wn[idx]  = sqrtf(s);
                else                g_xn2[idx] = s;
            }
        }
    }

    // ===== S0b: mega GEMMs x @ [centroids; W_hall; W_sel]^T  (512 items, klen 256) =====
    for (int item = bid * 4 + gid; item < 64 * KSA; item += NB * 4) {
        const int t = item & 63, ks = item >> 6;
        const float* Bm; float* P; int Nn, n0, ldp;
        if (t < 16)      { Bm = centroids; P = g_p_dot[ks];  Nn = C_; n0 = t * 64;        ldp = CP; }
        else if (t < 32) { Bm = W_hall;    P = g_p_hall[ks]; Nn = C_; n0 = (t - 16) * 64; ldp = CP; }
        else             { Bm = W_sel;     P = g_p_sel[ks];  Nn = F_; n0 = (t - 32) * 64; ldp = F_; }
        group_nt_hmma(x, F_, Bm, F_, P, ldp, Nn, n0, ks * 256, 256, gsm, gt, barid);
    }
    grid_sync(0);

    // ===== S1: reduce dot/hall, min-dist, softmax, reachability (64 blocks) =====
    if (bid < B_) {
        const int b = bid, c = tid;
        const bool val = c < C_;
        float hv = -1e30f, d2 = 1e30f;
        if (val) {
            float dot = 0.f, h = 0.f;
#pragma unroll
            for (int s = 0; s < KSA; s++) {
                dot += g_p_dot[s][b * CP + c];
                h   += g_p_hall[s][b * CP + c];
            }
            hv = h + b_hall[c];
            d2 = g_xn2[b] + g_cn2[c] - 2.f * dot;
        }
        float md2 = blk_min(d2, red);
        float mh  = blk_max(hv, red);
        float e   = val ? __expf(hv - mh) : 0.f;
        float se  = blk_sum(e, red);
        g_vm[b * CP + c] = e / se;     // c >= C_ writes 0 -> pad for mem gemm
        if (tid == 0) g_reach[b] = 10.f / sqrtf(fmaxf(md2, 1e-30f));
    }
    grid_sync(1);

    // ===== S2: memory_feature = vm @ centroids  (512 items, klen 64 over padded CP) =====
    for (int item = bid * 4 + gid; item < 32 * KSM; item += NB * 4) {
        const int nt = item & 31, ks = item >> 5;
        group_nn_hmma(g_vm, CP, centroids, F_, g_p_mem[ks], F_, nt * 64, ks * 64,
                      gsm, gt, barid);
    }
    grid_sync(2);

    // ===== S3: feat = reach*(x + tanh(sel)*mem), outputs, row norm (64 blocks) =====
    if (bid < B_) {
        const int b = bid;
        const float reach = g_reach[b];
        float n2 = 0.f;
#pragma unroll
        for (int f = tid; f < F_; f += 1024) {
            float mem = 0.f, sz = 0.f;
#pragma unroll
            for (int s = 0; s < KSM; s++) mem += g_p_mem[s][b * F_ + f];
#pragma unroll
            for (int s = 0; s < KSA; s++) sz  += g_p_sel[s][b * F_ + f];
            float sel  = tanhf(sz + b_sel[f]);
            float xv   = x[(size_t)b * F_ + f];
            float inf  = sel * mem;
            float feat = reach * (xv + inf);
            g_feat[b * F_ + f] = feat;
            n2 += feat * feat;
            if (writeFeat) {
                out[64000 + b * F_ + f]  = xv;   // direct_feature
                out[195072 + b * F_ + f] = inf;  // infused_feature
            }
        }
        float tot = blk_sum(n2, red);
        if (tid == 0) g_scale[b] = 16.f / (1.f + sqrtf(tot));
    }
    grid_sync(3);

    // ===== S4: cos logits GEMM feat @ W_cos^T  (512 items, klen 64) =====
    for (int item = bid * 4 + gid; item < 16 * KSC; item += NB * 4) {
        const int nt = item & 15, ks = item >> 4;
        group_nt_hmma(g_feat, F_, W_cos, F_, g_p_cos[ks], CP, C_, nt * 64, ks * 64, 64,
                      gsm, gt, barid);
    }
    grid_sync(4);

    // ===== S5: final scaled logits =====
    {
        const int i = bid * 1024 + tid;
        if (i < B_ * C_) {
            const int b = i / C_, c = i - b * C_;
            float s = 0.f;
#pragma unroll
            for (int ss = 0; ss < KSC; ss++) s += g_p_cos[ss][b * CP + c];
            out[i] = s * g_scale[b] / g_wn[c];
        }
    }
}

// ================= launch =================
#define DSM_BYTES (4 * 4 * GSM_F * 2)   // 4 groups * 4 arrays * 64*72 bf16 = 147456 B

extern "C" void kernel_launch(void* const* d_in, const int* in_sizes, int n_in,
                              void* d_out, int out_size) {
    const float* x         = (const float*)d_in[0];
    const float* centroids = (const float*)d_in[1];
    const float* W_hall    = (const float*)d_in[2];
    const float* b_hall    = (const float*)d_in[3];
    const float* W_sel     = (const float*)d_in[4];
    const float* b_sel     = (const float*)d_in[5];
    const float* W_cos     = (const float*)d_in[6];
    float* out = (float*)d_out;

    cudaFuncSetAttribute(fused_all, cudaFuncAttributeMaxDynamicSharedMemorySize, DSM_BYTES);

    int writeFeat = (out_size >= 326144) ? 1 : 0;
    fused_all<<<NB, 1024, DSM_BYTES>>>(x, centroids, W_hall, b_hall, W_sel, b_sel, W_cos,
                                       out, writeFeat);
}

// round 9
// speedup vs baseline: 2.0414x; 1.0102x over previous
#include <cuda_runtime.h>
#include <cuda_bf16.h>
#include <math.h>
#include <stdint.h>

#define B_   64
#define C_   1000
#define F_   2048
#define CP   1024
#define NB   148
#define KSA  8
#define KSM  16
#define KSC  32
#define KT   32                 // k-tile
#define GA   (64 * 36)          // bf16 elems per tile array
#define GRP  (4 * GA)           // elems per buffer (Ah,Al,Bh,Bl)
typedef unsigned long long ull;
typedef __nv_bfloat16 bf16;

// ---------------- scratch ----------------
__device__ __align__(256) float g_p_dot[KSA][B_ * CP];
__device__ __align__(256) float g_p_hall[KSA][B_ * CP];
__device__ __align__(256) float g_p_sel[KSA][B_ * F_];
__device__ __align__(256) float g_p_mem[KSM][B_ * F_];
__device__ __align__(256) float g_p_cos[KSC][B_ * CP];
__device__ __align__(256) float g_vm[B_ * CP];
__device__ __align__(256) float g_feat[B_ * F_];
__device__ float g_cn2[CP];
__device__ float g_wn[CP];
__device__ float g_xn2[B_];
__device__ float g_reach[B_];
__device__ float g_scale[B_];
__device__ float g_n2p[128];
__device__ unsigned int g_arr[8];
__device__ unsigned int g_flag[8];

// ---------------- barriers ----------------
__device__ __forceinline__ void gbar(int id) {
    asm volatile("bar.sync %0, 256;" :: "r"(id) : "memory");
}
__device__ __forceinline__ void grid_sync(int s) {
    __threadfence();
    __syncthreads();
    if (threadIdx.x == 0) {
        unsigned int before = atomicOr(&g_flag[s], 0u);
        unsigned int old = atomicAdd(&g_arr[s], 1u);
        if (old == NB - 1) {
            g_arr[s] = 0;
            __threadfence();
            atomicAdd(&g_flag[s], 1u);
        } else {
            while (atomicOr(&g_flag[s], 0u) == before) __nanosleep(64);
        }
    }
    __syncthreads();
    __threadfence();
}

// ---------------- block reductions (1024 threads) ----------------
__device__ __forceinline__ float blk_sum(float v, float* red) {
#pragma unroll
    for (int o = 16; o; o >>= 1) v += __shfl_xor_sync(0xffffffffu, v, o);
    if ((threadIdx.x & 31) == 0) red[threadIdx.x >> 5] = v;
    __syncthreads();
    if (threadIdx.x < 32) {
        float s = red[threadIdx.x];
#pragma unroll
        for (int o = 16; o; o >>= 1) s += __shfl_xor_sync(0xffffffffu, s, o);
        if (threadIdx.x == 0) red[0] = s;
    }
    __syncthreads();
    float r = red[0];
    __syncthreads();
    return r;
}
__device__ __forceinline__ float blk_min(float v, float* red) {
#pragma unroll
    for (int o = 16; o; o >>= 1) v = fminf(v, __shfl_xor_sync(0xffffffffu, v, o));
    if ((threadIdx.x & 31) == 0) red[threadIdx.x >> 5] = v;
    __syncthreads();
    if (threadIdx.x < 32) {
        float s = red[threadIdx.x];
#pragma unroll
        for (int o = 16; o; o >>= 1) s = fminf(s, __shfl_xor_sync(0xffffffffu, s, o));
        if (threadIdx.x == 0) red[0] = s;
    }
    __syncthreads();
    float r = red[0];
    __syncthreads();
    return r;
}
__device__ __forceinline__ float blk_max(float v, float* red) {
#pragma unroll
    for (int o = 16; o; o >>= 1) v = fmaxf(v, __shfl_xor_sync(0xffffffffu, v, o));
    if ((threadIdx.x & 31) == 0) red[threadIdx.x >> 5] = v;
    __syncthreads();
    if (threadIdx.x < 32) {
        float s = red[threadIdx.x];
#pragma unroll
        for (int o = 16; o; o >>= 1) s = fmaxf(s, __shfl_xor_sync(0xffffffffu, s, o));
        if (threadIdx.x == 0) red[0] = s;
    }
    __syncthreads();
    float r = red[0];
    __syncthreads();
    return r;
}

// ---------------- bf16 hi/lo conversion ----------------
__device__ __forceinline__ void cvt_hilo(float4 v, uint2& hi, uint2& lo) {
    uint32_t bx = __float_as_uint(v.x), by = __float_as_uint(v.y);
    uint32_t bz = __float_as_uint(v.z), bw = __float_as_uint(v.w);
    hi.x = __byte_perm(bx, by, 0x7632);
    hi.y = __byte_perm(bz, bw, 0x7632);
    float rx = v.x - __uint_as_float(bx & 0xffff0000u);
    float ry = v.y - __uint_as_float(by & 0xffff0000u);
    float rz = v.z - __uint_as_float(bz & 0xffff0000u);
    float rw = v.w - __uint_as_float(bw & 0xffff0000u);
    asm("cvt.rn.bf16x2.f32 %0, %1, %2;" : "=r"(lo.x) : "f"(ry), "f"(rx));
    asm("cvt.rn.bf16x2.f32 %0, %1, %2;" : "=r"(lo.y) : "f"(rw), "f"(rz));
}
__device__ __forceinline__ void cvt_hilo1(float v, bf16& h, bf16& l) {
    uint32_t b = __float_as_uint(v);
    unsigned short hs = (unsigned short)(b >> 16);
    h = *(bf16*)&hs;
    float r = v - __uint_as_float(b & 0xffff0000u);
    l = __float2bfloat16_rn(r);
}

__device__ __forceinline__ void mma16816(float* d,
                                         uint32_t a0, uint32_t a1, uint32_t a2, uint32_t a3,
                                         uint32_t b0, uint32_t b1) {
    asm volatile("mma.sync.aligned.m16n8k16.row.col.f32.bf16.bf16.f32 "
        "{%0,%1,%2,%3}, {%4,%5,%6,%7}, {%8,%9}, {%0,%1,%2,%3};"
        : "+f"(d[0]), "+f"(d[1]), "+f"(d[2]), "+f"(d[3])
        : "r"(a0), "r"(a1), "r"(a2), "r"(a3), "r"(b0), "r"(b1));
}

// ---------------- HMMA over one 64x64x32 hi/lo tile (one buffer) ----------------
__device__ __forceinline__ void tile_hmma32(const bf16* buf, int m0, int nh,
                                            int fr, int fc, float acc[4][4]) {
    const bf16* Ah = buf;
    const bf16* Al = buf + GA;
    const bf16* Bh = buf + 2 * GA;
    const bf16* Bl = buf + 3 * GA;
#pragma unroll
    for (int kk = 0; kk < 2; kk++) {
        const int kc = kk * 16 + fc;
        uint32_t ah0 = *(const uint32_t*)&Ah[(m0 + fr) * 36 + kc];
        uint32_t ah1 = *(const uint32_t*)&Ah[(m0 + fr + 8) * 36 + kc];
        uint32_t ah2 = *(const uint32_t*)&Ah[(m0 + fr) * 36 + kc + 8];
        uint32_t ah3 = *(const uint32_t*)&Ah[(m0 + fr + 8) * 36 + kc + 8];
        uint32_t al0 = *(const uint32_t*)&Al[(m0 + fr) * 36 + kc];
        uint32_t al1 = *(const uint32_t*)&Al[(m0 + fr + 8) * 36 + kc];
        uint32_t al2 = *(const uint32_t*)&Al[(m0 + fr) * 36 + kc + 8];
        uint32_t al3 = *(const uint32_t*)&Al[(m0 + fr + 8) * 36 + kc + 8];
#pragma unroll
        for (int nt = 0; nt < 4; nt++) {
            const int bn = (nh + nt * 8 + fr) * 36;
            uint32_t bh0 = *(const uint32_t*)&Bh[bn + kc];
            uint32_t bh1 = *(const uint32_t*)&Bh[bn + kc + 8];
            uint32_t bl0 = *(const uint32_t*)&Bl[bn + kc];
            uint32_t bl1 = *(const uint32_t*)&Bl[bn + kc + 8];
            mma16816(acc[nt], ah0, ah1, ah2, ah3, bh0, bh1);
            mma16816(acc[nt], ah0, ah1, ah2, ah3, bl0, bl1);
            mma16816(acc[nt], al0, al1, al2, al3, bh0, bh1);
        }
    }
}

__device__ __forceinline__ void store_acc(float* __restrict__ P, int ldp, int n0,
                                          int m0, int nh, int fr, int fc,
                                          float acc[4][4]) {
#pragma unroll
    for (int nt = 0; nt < 4; nt++) {
        const int n = n0 + nh + nt * 8 + fc;
        *(float2*)&P[(size_t)(m0 + fr) * ldp + n]     = make_float2(acc[nt][0], acc[nt][1]);
        *(float2*)&P[(size_t)(m0 + fr + 8) * ldp + n] = make_float2(acc[nt][2], acc[nt][3]);
    }
}

// NT: P[m, n0+n] = sum_k A[m,k] * Bm[n0+n, k]; double-buffered, reg prefetch.
__device__ __forceinline__ void group_nt_hmma(const float* __restrict__ A, int lda,
                                              const float* __restrict__ Bm, int ldb,
                                              float* __restrict__ P, int ldp,
                                              int Nn, int n0, int k0, int klen,
                                              bf16* gsm, int gt, int barid) {
    const int lane = gt & 31, wg = gt >> 5;
    const int m0 = (wg & 3) * 16, nh = (wg >> 2) * 32;
    const int fr = lane >> 2, fc = (lane & 3) * 2;
    const int row = gt >> 2, kq = (gt & 3) * 8;
    const bool bv = (n0 + row) < Nn;
    const float* Arow = A + (size_t)row * lda + k0 + kq;
    const float* Brow = Bm + (size_t)(n0 + row) * ldb + k0 + kq;
    const int T = klen >> 5;

    float acc[4][4];
#pragma unroll
    for (int i = 0; i < 4; i++)
#pragma unroll
        for (int j = 0; j < 4; j++) acc[i][j] = 0.f;

    float4 a0, a1, b0, b1;
    a0 = *(const float4*)(Arow);
    a1 = *(const float4*)(Arow + 4);
    if (bv) { b0 = *(const float4*)(Brow); b1 = *(const float4*)(Brow + 4); }
    else    { b0 = make_float4(0,0,0,0); b1 = b0; }
    {
        bf16* Ah = gsm; bf16* Al = gsm + GA; bf16* Bh = gsm + 2*GA; bf16* Bl = gsm + 3*GA;
        uint2 h, l;
        cvt_hilo(a0, h, l); *(uint2*)&Ah[row*36+kq] = h; *(uint2*)&Al[row*36+kq] = l;
        cvt_hilo(a1, h, l); *(uint2*)&Ah[row*36+kq+4] = h; *(uint2*)&Al[row*36+kq+4] = l;
        cvt_hilo(b0, h, l); *(uint2*)&Bh[row*36+kq] = h; *(uint2*)&Bl[row*36+kq] = l;
        cvt_hilo(b1, h, l); *(uint2*)&Bh[row*36+kq+4] = h; *(uint2*)&Bl[row*36+kq+4] = l;
    }
    gbar(barid);

    for (int t = 0; t < T; t++) {
        const bool hn = (t + 1) < T;
        if (hn) {
            const float* ap = Arow + (t + 1) * KT;
            a0 = *(const float4*)(ap); a1 = *(const float4*)(ap + 4);
            if (bv) {
                const float* bp = Brow + (t + 1) * KT;
                b0 = *(const float4*)(bp); b1 = *(const float4*)(bp + 4);
            }
        }
        tile_hmma32(gsm + (t & 1) * GRP, m0, nh, fr, fc, acc);
        if (hn) {
            bf16* dst = gsm + ((t + 1) & 1) * GRP;
            bf16* Ah = dst; bf16* Al = dst + GA; bf16* Bh = dst + 2*GA; bf16* Bl = dst + 3*GA;
            uint2 h, l;
            cvt_hilo(a0, h, l); *(uint2*)&Ah[row*36+kq] = h; *(uint2*)&Al[row*36+kq] = l;
            cvt_hilo(a1, h, l); *(uint2*)&Ah[row*36+kq+4] = h; *(uint2*)&Al[row*36+kq+4] = l;
            cvt_hilo(b0, h, l); *(uint2*)&Bh[row*36+kq] = h; *(uint2*)&Bl[row*36+kq] = l;
            cvt_hilo(b1, h, l); *(uint2*)&Bh[row*36+kq+4] = h; *(uint2*)&Bl[row*36+kq+4] = l;
            gbar(barid);
        }
    }
    store_acc(P, ldp, n0, m0, nh, fr, fc, acc);
}

// NN: P[m, n0+n] = sum_k A[m,k] * Bm[k, n0+n]; Bm k-rows guarded < C_.
__device__ __forceinline__ void group_nn_hmma(const float* __restrict__ A, int lda,
                                              const float* __restrict__ Bm, int ldb,
                                              float* __restrict__ P, int ldp,
                                              int n0, int k0, int klen,
                                              bf16* gsm, int gt, int barid) {
    const int lane = gt & 31, wg = gt >> 5;
    const int m0 = (wg & 3) * 16, nh = (wg >> 2) * 32;
    const int fr = lane >> 2, fc = (lane & 3) * 2;
    const int row = gt >> 2, kq = (gt & 3) * 8;
    const int krl = gt >> 3, nq = (gt & 7) * 8;
    const int T = klen >> 5;
    const float* Arow = A + (size_t)row * lda + k0 + kq;

    float acc[4][4];
#pragma unroll
    for (int i = 0; i < 4; i++)
#pragma unroll
        for (int j = 0; j < 4; j++) acc[i][j] = 0.f;

    float4 a0, a1, b0, b1;
    auto ldb_t = [&](int t, float4& v0, float4& v1) {
        int krow = k0 + t * KT + krl;
        if (krow < C_) {
            const float* bp = Bm + (size_t)krow * ldb + n0 + nq;
            v0 = *(const float4*)(bp); v1 = *(const float4*)(bp + 4);
        } else { v0 = make_float4(0,0,0,0); v1 = v0; }
    };
    auto stt = [&](int buf, float4 va0, float4 va1, float4 vb0, float4 vb1) {
        bf16* dst = gsm + buf * GRP;
        bf16* Ah = dst; bf16* Al = dst + GA; bf16* Bh = dst + 2*GA; bf16* Bl = dst + 3*GA;
        uint2 h, l;
        cvt_hilo(va0, h, l); *(uint2*)&Ah[row*36+kq] = h; *(uint2*)&Al[row*36+kq] = l;
        cvt_hilo(va1, h, l); *(uint2*)&Ah[row*36+kq+4] = h; *(uint2*)&Al[row*36+kq+4] = l;
        const float bs[8] = {vb0.x, vb0.y, vb0.z, vb0.w, vb1.x, vb1.y, vb1.z, vb1.w};
#pragma unroll
        for (int j = 0; j < 8; j++) {
            bf16 hh, ll;
            cvt_hilo1(bs[j], hh, ll);
            Bh[(nq + j) * 36 + krl] = hh;
            Bl[(nq + j) * 36 + krl] = ll;
        }
    };

    a0 = *(const float4*)(Arow); a1 = *(const float4*)(Arow + 4);
    ldb_t(0, b0, b1);
    stt(0, a0, a1, b0, b1);
    gbar(barid);

    for (int t = 0; t < T; t++) {
        const bool hn = (t + 1) < T;
        if (hn) {
            const float* ap = Arow + (t + 1) * KT;
            a0 = *(const float4*)(ap); a1 = *(const float4*)(ap + 4);
            ldb_t(t + 1, b0, b1);
        }
        tile_hmma32(gsm + (t & 1) * GRP, m0, nh, fr, fc, acc);
        if (hn) { stt((t + 1) & 1, a0, a1, b0, b1); gbar(barid); }
    }
    store_acc(P, ldp, n0, m0, nh, fr, fc, acc);
}

// ---------------- the single fused persistent kernel ----------------
__global__ void __launch_bounds__(1024, 1)
fused_all(const float* __restrict__ x,
          const float* __restrict__ centroids,
          const float* __restrict__ W_hall,
          const float* __restrict__ b_hall,
          const float* __restrict__ W_sel,
          const float* __restrict__ b_sel,
          const float* __restrict__ W_cos,
          float* __restrict__ out, int writeFeat) {
    extern __shared__ __align__(16) bf16 dsm[];   // 4 groups * 2 buffers * GRP
    __shared__ float red[32];
    const int tid = threadIdx.x, bid = blockIdx.x;
    const int gid = tid >> 8, gt = tid & 255, barid = gid + 1;
    bf16* gsm = dsm + gid * 2 * GRP;

    // ===== S0a: row norms (one row per warp) =====
    {
        const int gw = bid * 32 + (tid >> 5);
        const int lane = tid & 31;
        if (gw < 2064) {
            const float* src; int mode, idx;
            if (gw < 1000)      { src = centroids + (size_t)gw * F_;      mode = 0; idx = gw; }
            else if (gw < 2000) { src = W_cos + (size_t)(gw - 1000) * F_; mode = 1; idx = gw - 1000; }
            else                { src = x + (size_t)(gw - 2000) * F_;     mode = 2; idx = gw - 2000; }
            const float4* s4 = (const float4*)src;
            float s = 0.f;
            for (int i = lane; i < F_ / 4; i += 32) {
                float4 v = s4[i];
                s += v.x * v.x + v.y * v.y + v.z * v.z + v.w * v.w;
            }
#pragma unroll
            for (int o = 16; o; o >>= 1) s += __shfl_xor_sync(0xffffffffu, s, o);
            if (lane == 0) {
                if (mode == 0)      g_cn2[idx] = s;
                else if (mode == 1) g_wn[idx]  = sqrtf(s);
                else                g_xn2[idx] = s;
            }
        }
    }

    // ===== S0b: mega GEMMs x @ [centroids; W_hall; W_sel]^T  (512 items, klen 256) =====
    {
        const int item = bid * 4 + gid;
        if (item < 64 * KSA) {
            const int t = item & 63, ks = item >> 6;
            const float* Bm; float* P; int Nn, n0, ldp;
            if (t < 16)      { Bm = centroids; P = g_p_dot[ks];  Nn = C_; n0 = t * 64;        ldp = CP; }
            else if (t < 32) { Bm = W_hall;    P = g_p_hall[ks]; Nn = C_; n0 = (t - 16) * 64; ldp = CP; }
            else             { Bm = W_sel;     P = g_p_sel[ks];  Nn = F_; n0 = (t - 32) * 64; ldp = F_; }
            group_nt_hmma(x, F_, Bm, F_, P, ldp, Nn, n0, ks * 256, 256, gsm, gt, barid);
        }
    }
    grid_sync(0);

    // ===== S1: reduce dot/hall, min-dist, softmax, reachability (64 blocks, float2) =====
    if (bid < B_) {
        const int b = bid;
        const int c0 = tid * 2;
        const bool val = (tid < 500);
        float hv0 = -1e30f, hv1 = -1e30f, d2m = 1e30f;
        if (val) {
            float2 dot = make_float2(0.f, 0.f), h = make_float2(0.f, 0.f);
#pragma unroll
            for (int s = 0; s < KSA; s++) {
                float2 d = *(const float2*)&g_p_dot[s][b * CP + c0];
                float2 hh = *(const float2*)&g_p_hall[s][b * CP + c0];
                dot.x += d.x; dot.y += d.y; h.x += hh.x; h.y += hh.y;
            }
            float2 bh = *(const float2*)&b_hall[c0];
            hv0 = h.x + bh.x; hv1 = h.y + bh.y;
            float xn2 = g_xn2[b];
            float d20 = xn2 + g_cn2[c0] - 2.f * dot.x;
            float d21 = xn2 + g_cn2[c0 + 1] - 2.f * dot.y;
            d2m = fminf(d20, d21);
        }
        float md2 = blk_min(d2m, red);
        float mh  = blk_max(fmaxf(hv0, hv1), red);
        float e0 = val ? __expf(hv0 - mh) : 0.f;
        float e1 = val ? __expf(hv1 - mh) : 0.f;
        float se = blk_sum(e0 + e1, red);
        if (tid < 512) {
            float inv = 1.f / se;
            float2 w = val ? make_float2(e0 * inv, e1 * inv) : make_float2(0.f, 0.f);
            *(float2*)&g_vm[b * CP + c0] = w;   // tid 500..511 zero-pad 1000..1023
        }
        if (tid == 0) g_reach[b] = 10.f / sqrtf(fmaxf(md2, 1e-30f));
    }
    grid_sync(1);

    // ===== S2: memory_feature = vm @ centroids  (512 items, klen 64) =====
    {
        const int item = bid * 4 + gid;
        if (item < 32 * KSM) {
            const int nt = item & 31, ks = item >> 5;
            group_nn_hmma(g_vm, CP, centroids, F_, g_p_mem[ks], F_, nt * 64, ks * 64, 64,
                          gsm, gt, barid);
        }
    }
    grid_sync(2);

    // ===== S3: feat = reach*(x + tanh(sel)*mem) on 128 blocks (half row each) =====
    if (bid < 128) {
        const int b = bid >> 1;
        const int f = (bid & 1) * 1024 + tid;
        const float reach = g_reach[b];
        float mem = 0.f, sz = 0.f;
#pragma unroll
        for (int s = 0; s < KSM; s++) mem += g_p_mem[s][b * F_ + f];
#pragma unroll
        for (int s = 0; s < KSA; s++) sz  += g_p_sel[s][b * F_ + f];
        float sel  = tanhf(sz + b_sel[f]);
        float xv   = x[(size_t)b * F_ + f];
        float inf  = sel * mem;
        float feat = reach * (xv + inf);
        g_feat[b * F_ + f] = feat;
        if (writeFeat) {
            out[64000 + b * F_ + f]  = xv;   // direct_feature
            out[195072 + b * F_ + f] = inf;  // infused_feature
        }
        float n2 = blk_sum(feat * feat, red);
        if (tid == 0) g_n2p[bid] = n2;
    }
    grid_sync(3);

    // ===== S4: cos logits GEMM feat @ W_cos^T (512 items) + scale reduce on idle block =====
    {
        const int item = bid * 4 + gid;
        if (item < 16 * KSC) {
            const int nt = item & 15, ks = item >> 4;
            group_nt_hmma(g_feat, F_, W_cos, F_, g_p_cos[ks], CP, C_, nt * 64, ks * 64, 64,
                          gsm, gt, barid);
        }
    }
    if (bid == NB - 1 && tid < B_) {
        float n2 = g_n2p[2 * tid] + g_n2p[2 * tid + 1];
        g_scale[tid] = 16.f / (1.f + sqrtf(n2));
    }
    grid_sync(4);

    // ===== S5: final scaled logits =====
    {
        const int i = bid * 1024 + tid;
        if (i < B_ * C_) {
            const int b = i / C_, c = i - b * C_;
            float s = 0.f;
#pragma unroll
            for (int ss = 0; ss < KSC; ss++) s += g_p_cos[ss][b * CP + c];
            out[i] = s * g_scale[b] / g_wn[c];
        }
    }
}

// ================= launch =================
#define DSM_BYTES (4 * 2 * GRP * 2)   // 4 groups * 2 buffers * 4 arrays * 64*36 bf16 = 147456 B

extern "C" void kernel_launch(void* const* d_in, const int* in_sizes, int n_in,
                              void* d_out, int out_size) {
    const float* x         = (const float*)d_in[0];
    const float* centroids = (const float*)d_in[1];
    const float* W_hall    = (const float*)d_in[2];
    const float* b_hall    = (const float*)d_in[3];
    const float* W_sel     = (const float*)d_in[4];
    const float* b_sel     = (const float*)d_in[5];
    const float* W_cos     = (const float*)d_in[6];
    float* out = (float*)d_out;

    cudaFuncSetAttribute(fused_all, cudaFuncAttributeMaxDynamicSharedMemorySize, DSM_BYTES);

    int writeFeat = (out_size >= 326144) ? 1 : 0;
    fused_all<<<NB, 1024, DSM_BYTES>>>(x, centroids, W_hall, b_hall, W_sel, b_sel, W_cos,
                                       out, writeFeat);
}

// round 10
// speedup vs baseline: 2.3235x; 1.1382x over previous
#include <cuda_runtime.h>
#include <cuda_fp16.h>
#include <math.h>
#include <stdint.h>

#define B_   64
#define C_   1000
#define F_   2048
#define CP   1024
#define NB   148
#define KSA  8
#define KSM  16
#define KSC  32
#define KT   32
#define GA   (64 * 40)          // halves per tile array (row stride 40)
#define GRP  (3 * GA)           // Ah, Al, Bh
typedef unsigned long long ull;

// ---------------- scratch ----------------
__device__ __align__(256) float g_p_dot[KSA][B_ * CP];
__device__ __align__(256) float g_p_hall[KSA][B_ * CP];
__device__ __align__(256) float g_p_sel[KSA][B_ * F_];
__device__ __align__(256) float g_p_mem[KSM][B_ * F_];
__device__ __align__(256) float g_p_cos[KSC][B_ * CP];
__device__ __align__(256) __half g_xh[B_ * F_];
__device__ __align__(256) __half g_xl[B_ * F_];
__device__ __align__(256) __half g_vmh[B_ * CP];
__device__ __align__(256) __half g_vml[B_ * CP];
__device__ __align__(256) __half g_fh[B_ * F_];
__device__ __align__(256) __half g_fl[B_ * F_];
__device__ float g_cn2[CP];
__device__ float g_wn[CP];
__device__ float g_xn2[B_];
__device__ float g_reach[B_];
__device__ float g_scale[B_];
__device__ float g_n2p[128];
__device__ unsigned int g_arr[8];
__device__ unsigned int g_flag[8];

// ---------------- barriers ----------------
__device__ __forceinline__ void gbar(int id) {
    asm volatile("bar.sync %0, 256;" :: "r"(id) : "memory");
}
__device__ __forceinline__ void grid_sync(int s) {
    __threadfence();
    __syncthreads();
    if (threadIdx.x == 0) {
        unsigned int before = atomicOr(&g_flag[s], 0u);
        unsigned int old = atomicAdd(&g_arr[s], 1u);
        if (old == NB - 1) {
            g_arr[s] = 0;
            __threadfence();
            atomicAdd(&g_flag[s], 1u);
        } else {
            while (atomicOr(&g_flag[s], 0u) == before) __nanosleep(64);
        }
    }
    __syncthreads();
    __threadfence();
}

// ---------------- block reductions (1024 threads) ----------------
__device__ __forceinline__ float blk_sum(float v, float* red) {
#pragma unroll
    for (int o = 16; o; o >>= 1) v += __shfl_xor_sync(0xffffffffu, v, o);
    if ((threadIdx.x & 31) == 0) red[threadIdx.x >> 5] = v;
    __syncthreads();
    if (threadIdx.x < 32) {
        float s = red[threadIdx.x];
#pragma unroll
        for (int o = 16; o; o >>= 1) s += __shfl_xor_sync(0xffffffffu, s, o);
        if (threadIdx.x == 0) red[0] = s;
    }
    __syncthreads();
    float r = red[0];
    __syncthreads();
    return r;
}
__device__ __forceinline__ float blk_min(float v, float* red) {
#pragma unroll
    for (int o = 16; o; o >>= 1) v = fminf(v, __shfl_xor_sync(0xffffffffu, v, o));
    if ((threadIdx.x & 31) == 0) red[threadIdx.x >> 5] = v;
    __syncthreads();
    if (threadIdx.x < 32) {
        float s = red[threadIdx.x];
#pragma unroll
        for (int o = 16; o; o >>= 1) s = fminf(s, __shfl_xor_sync(0xffffffffu, s, o));
        if (threadIdx.x == 0) red[0] = s;
    }
    __syncthreads();
    float r = red[0];
    __syncthreads();
    return r;
}
__device__ __forceinline__ float blk_max(float v, float* red) {
#pragma unroll
    for (int o = 16; o; o >>= 1) v = fmaxf(v, __shfl_xor_sync(0xffffffffu, v, o));
    if ((threadIdx.x & 31) == 0) red[threadIdx.x >> 5] = v;
    __syncthreads();
    if (threadIdx.x < 32) {
        float s = red[threadIdx.x];
#pragma unroll
        for (int o = 16; o; o >>= 1) s = fmaxf(s, __shfl_xor_sync(0xffffffffu, s, o));
        if (threadIdx.x == 0) red[0] = s;
    }
    __syncthreads();
    float r = red[0];
    __syncthreads();
    return r;
}

// ---------------- fp16 pack ----------------
__device__ __forceinline__ uint32_t f16pack(float lo, float hi) {
    uint32_t r;
    asm("cvt.rn.f16x2.f32 %0, %1, %2;" : "=r"(r) : "f"(hi), "f"(lo));
    return r;
}
__device__ __forceinline__ void hilo1(float v, __half& h, __half& l) {
    h = __float2half_rn(v);
    l = __float2half_rn(v - __half2float(h));
}

__device__ __forceinline__ void mma16816(float* d,
                                         uint32_t a0, uint32_t a1, uint32_t a2, uint32_t a3,
                                         uint32_t b0, uint32_t b1) {
    asm volatile("mma.sync.aligned.m16n8k16.row.col.f32.f16.f16.f32 "
        "{%0,%1,%2,%3}, {%4,%5,%6,%7}, {%8,%9}, {%0,%1,%2,%3};"
        : "+f"(d[0]), "+f"(d[1]), "+f"(d[2]), "+f"(d[3])
        : "r"(a0), "r"(a1), "r"(a2), "r"(a3), "r"(b0), "r"(b1));
}

// ---------------- mma phase over one 64x64x32 tile: acc += (Ah+Al)*Bh ----------------
__device__ __forceinline__ void tile_f16(const __half* buf, int m0, int nh,
                                         int fr, int fc, float acc[4][4]) {
    const __half* Ah = buf;
    const __half* Al = buf + GA;
    const __half* Bh = buf + 2 * GA;
#pragma unroll
    for (int kk = 0; kk < 2; kk++) {
        const int kc = kk * 16 + fc;
        uint32_t ah0 = *(const uint32_t*)&Ah[(m0 + fr) * 40 + kc];
        uint32_t ah1 = *(const uint32_t*)&Ah[(m0 + fr + 8) * 40 + kc];
        uint32_t ah2 = *(const uint32_t*)&Ah[(m0 + fr) * 40 + kc + 8];
        uint32_t ah3 = *(const uint32_t*)&Ah[(m0 + fr + 8) * 40 + kc + 8];
        uint32_t al0 = *(const uint32_t*)&Al[(m0 + fr) * 40 + kc];
        uint32_t al1 = *(const uint32_t*)&Al[(m0 + fr + 8) * 40 + kc];
        uint32_t al2 = *(const uint32_t*)&Al[(m0 + fr) * 40 + kc + 8];
        uint32_t al3 = *(const uint32_t*)&Al[(m0 + fr + 8) * 40 + kc + 8];
#pragma unroll
        for (int nt = 0; nt < 4; nt++) {
            const int bn = (nh + nt * 8 + fr) * 40;
            uint32_t bh0 = *(const uint32_t*)&Bh[bn + kc];
            uint32_t bh1 = *(const uint32_t*)&Bh[bn + kc + 8];
            mma16816(acc[nt], ah0, ah1, ah2, ah3, bh0, bh1);
            mma16816(acc[nt], al0, al1, al2, al3, bh0, bh1);
        }
    }
}

__device__ __forceinline__ void store_acc(float* __restrict__ P, int ldp, int n0,
                                          int m0, int nh, int fr, int fc,
                                          float acc[4][4]) {
#pragma unroll
    for (int nt = 0; nt < 4; nt++) {
        const int n = n0 + nh + nt * 8 + fc;
        *(float2*)&P[(size_t)(m0 + fr) * ldp + n]     = make_float2(acc[nt][0], acc[nt][1]);
        *(float2*)&P[(size_t)(m0 + fr + 8) * ldp + n] = make_float2(acc[nt][2], acc[nt][3]);
    }
}

// NT: P = A(fp16 h/l precomputed) @ B(fp32, cvt hi-only)^T
__device__ __forceinline__ void group_nt_f16(const __half* __restrict__ Ahg,
                                             const __half* __restrict__ Alg, int lda,
                                             const float* __restrict__ Bm, int ldb,
                                             float* __restrict__ P, int ldp,
                                             int Nn, int n0, int k0, int klen,
                                             __half* gsm, int gt, int barid) {
    const int lane = gt & 31, wg = gt >> 5;
    const int m0 = (wg & 3) * 16, nh = (wg >> 2) * 32;
    const int fr = lane >> 2, fc = (lane & 3) * 2;
    const int row = gt >> 2, kq = (gt & 3) * 8;
    const bool bv = (n0 + row) < Nn;
    const __half* Ah_p = Ahg + (size_t)row * lda + k0 + kq;
    const __half* Al_p = Alg + (size_t)row * lda + k0 + kq;
    const float*  B_p  = Bm + (size_t)(n0 + row) * ldb + k0 + kq;
    const int T = klen >> 5;

    float acc[4][4];
#pragma unroll
    for (int i = 0; i < 4; i++)
#pragma unroll
        for (int j = 0; j < 4; j++) acc[i][j] = 0.f;

    uint4 pah, pal; float4 pb0, pb1;
    pah = *(const uint4*)(Ah_p);
    pal = *(const uint4*)(Al_p);
    if (bv) { pb0 = *(const float4*)(B_p); pb1 = *(const float4*)(B_p + 4); }
    else    { pb0 = make_float4(0,0,0,0); pb1 = pb0; }
    {
        __half* d = gsm;
        *(uint4*)&d[row * 40 + kq]          = pah;
        *(uint4*)&d[GA + row * 40 + kq]     = pal;
        uint4 bp = make_uint4(f16pack(pb0.x, pb0.y), f16pack(pb0.z, pb0.w),
                              f16pack(pb1.x, pb1.y), f16pack(pb1.z, pb1.w));
        *(uint4*)&d[2 * GA + row * 40 + kq] = bp;
    }
    gbar(barid);

    for (int t = 0; t < T; t++) {
        const bool hn = (t + 1) < T;
        if (hn) {
            const int o = (t + 1) * KT;
            pah = *(const uint4*)(Ah_p + o);
            pal = *(const uint4*)(Al_p + o);
            if (bv) { pb0 = *(const float4*)(B_p + o); pb1 = *(const float4*)(B_p + o + 4); }
        }
        tile_f16(gsm + (t & 1) * GRP, m0, nh, fr, fc, acc);
        if (hn) {
            __half* d = gsm + ((t + 1) & 1) * GRP;
            *(uint4*)&d[row * 40 + kq]      = pah;
            *(uint4*)&d[GA + row * 40 + kq] = pal;
            uint4 bp = make_uint4(f16pack(pb0.x, pb0.y), f16pack(pb0.z, pb0.w),
                                  f16pack(pb1.x, pb1.y), f16pack(pb1.z, pb1.w));
            *(uint4*)&d[2 * GA + row * 40 + kq] = bp;
            gbar(barid);
        }
    }
    store_acc(P, ldp, n0, m0, nh, fr, fc, acc);
}

// NN: P = A(vm fp16 h/l) @ B(centroids fp32 k-major, cvt + transpose hi-only)
__device__ __forceinline__ void group_nn_f16(const __half* __restrict__ Ahg,
                                             const __half* __restrict__ Alg, int lda,
                                             const float* __restrict__ Bm, int ldb,
                                             float* __restrict__ P, int ldp,
                                             int n0, int k0, int klen,
                                             __half* gsm, int gt, int barid) {
    const int lane = gt & 31, wg = gt >> 5;
    const int m0 = (wg & 3) * 16, nh = (wg >> 2) * 32;
    const int fr = lane >> 2, fc = (lane & 3) * 2;
    const int row = gt >> 2, kq = (gt & 3) * 8;
    const int k2 = (gt & 15) * 2, nq = (gt >> 4) * 4;
    const __half* Ah_p = Ahg + (size_t)row * lda + k0 + kq;
    const __half* Al_p = Alg + (size_t)row * lda + k0 + kq;
    const int T = klen >> 5;

    float acc[4][4];
#pragma unroll
    for (int i = 0; i < 4; i++)
#pragma unroll
        for (int j = 0; j < 4; j++) acc[i][j] = 0.f;

    uint4 pah, pal; float4 pb0, pb1;
    auto ldB = [&](int t, float4& v0, float4& v1) {
        int kr0 = k0 + t * KT + k2;
        v0 = (kr0 < C_)     ? *(const float4*)&Bm[(size_t)kr0 * ldb + n0 + nq]       : make_float4(0,0,0,0);
        v1 = (kr0 + 1 < C_) ? *(const float4*)&Bm[(size_t)(kr0 + 1) * ldb + n0 + nq] : make_float4(0,0,0,0);
    };
    auto stT = [&](int buf, uint4 ah, uint4 al, float4 v0, float4 v1) {
        __half* d = gsm + buf * GRP;
        *(uint4*)&d[row * 40 + kq]      = ah;
        *(uint4*)&d[GA + row * 40 + kq] = al;
        __half* Bh = d + 2 * GA;
        *(uint32_t*)&Bh[(nq + 0) * 40 + k2] = f16pack(v0.x, v1.x);
        *(uint32_t*)&Bh[(nq + 1) * 40 + k2] = f16pack(v0.y, v1.y);
        *(uint32_t*)&Bh[(nq + 2) * 40 + k2] = f16pack(v0.z, v1.z);
        *(uint32_t*)&Bh[(nq + 3) * 40 + k2] = f16pack(v0.w, v1.w);
    };

    pah = *(const uint4*)(Ah_p);
    pal = *(const uint4*)(Al_p);
    ldB(0, pb0, pb1);
    stT(0, pah, pal, pb0, pb1);
    gbar(barid);

    for (int t = 0; t < T; t++) {
        const bool hn = (t + 1) < T;
        if (hn) {
            const int o = (t + 1) * KT;
            pah = *(const uint4*)(Ah_p + o);
            pal = *(const uint4*)(Al_p + o);
            ldB(t + 1, pb0, pb1);
        }
        tile_f16(gsm + (t & 1) * GRP, m0, nh, fr, fc, acc);
        if (hn) { stT((t + 1) & 1, pah, pal, pb0, pb1); gbar(barid); }
    }
    store_acc(P, ldp, n0, m0, nh, fr, fc, acc);
}

// ---------------- the single fused persistent kernel ----------------
__global__ void __launch_bounds__(1024, 1)
fused_all(const float* __restrict__ x,
          const float* __restrict__ centroids,
          const float* __restrict__ W_hall,
          const float* __restrict__ b_hall,
          const float* __restrict__ W_sel,
          const float* __restrict__ b_sel,
          const float* __restrict__ W_cos,
          float* __restrict__ out, int writeFeat) {
    extern __shared__ __align__(16) __half dsm[];   // 4 groups * 2 buffers * GRP
    __shared__ float red[32];
    const int tid = threadIdx.x, bid = blockIdx.x;
    const int gid = tid >> 8, gt = tid & 255, barid = gid + 1;
    __half* gsm = dsm + gid * 2 * GRP;

    // ===== S0a: x -> fp16 hi/lo =====
    {
        const int i = bid * 1024 + tid;
        if (i < B_ * F_) {
            __half h, l;
            hilo1(x[i], h, l);
            g_xh[i] = h; g_xl[i] = l;
        }
    }
    // ===== S0b: row norms (one row per warp) =====
    {
        const int gw = bid * 32 + (tid >> 5);
        const int lane = tid & 31;
        if (gw < 2064) {
            const float* src; int mode, idx;
            if (gw < 1000)      { src = centroids + (size_t)gw * F_;      mode = 0; idx = gw; }
            else if (gw < 2000) { src = W_cos + (size_t)(gw - 1000) * F_; mode = 1; idx = gw - 1000; }
            else                { src = x + (size_t)(gw - 2000) * F_;     mode = 2; idx = gw - 2000; }
            const float4* s4 = (const float4*)src;
            float s = 0.f;
            for (int i = lane; i < F_ / 4; i += 32) {
                float4 v = s4[i];
                s += v.x * v.x + v.y * v.y + v.z * v.z + v.w * v.w;
            }
#pragma unroll
            for (int o = 16; o; o >>= 1) s += __shfl_xor_sync(0xffffffffu, s, o);
            if (lane == 0) {
                if (mode == 0)      g_cn2[idx] = s;
                else if (mode == 1) g_wn[idx]  = sqrtf(s);
                else                g_xn2[idx] = s;
            }
        }
    }
    grid_sync(0);

    // ===== S1: mega GEMMs x @ [centroids; W_hall; W_sel]^T  (512 items, klen 256) =====
    {
        const int item = bid * 4 + gid;
        if (item < 64 * KSA) {
            const int t = item & 63, ks = item >> 6;
            const float* Bm; float* P; int Nn, n0, ldp;
            if (t < 16)      { Bm = centroids; P = g_p_dot[ks];  Nn = C_; n0 = t * 64;        ldp = CP; }
            else if (t < 32) { Bm = W_hall;    P = g_p_hall[ks]; Nn = C_; n0 = (t - 16) * 64; ldp = CP; }
            else             { Bm = W_sel;     P = g_p_sel[ks];  Nn = F_; n0 = (t - 32) * 64; ldp = F_; }
            group_nt_f16(g_xh, g_xl, F_, Bm, F_, P, ldp, Nn, n0, ks * 256, 256, gsm, gt, barid);
        }
    }
    grid_sync(1);

    // ===== S2: reduce dot/hall, min-dist, softmax, reachability (64 blocks) =====
    if (bid < B_) {
        const int b = bid;
        const int c0 = tid * 2;
        const bool val = (tid < 500);
        float hv0 = -1e30f, hv1 = -1e30f, d2m = 1e30f;
        if (val) {
            float2 dot = make_float2(0.f, 0.f), h = make_float2(0.f, 0.f);
#pragma unroll
            for (int s = 0; s < KSA; s++) {
                float2 d = *(const float2*)&g_p_dot[s][b * CP + c0];
                float2 hh = *(const float2*)&g_p_hall[s][b * CP + c0];
                dot.x += d.x; dot.y += d.y; h.x += hh.x; h.y += hh.y;
            }
            float2 bh = *(const float2*)&b_hall[c0];
            hv0 = h.x + bh.x; hv1 = h.y + bh.y;
            float xn2 = g_xn2[b];
            float d20 = xn2 + g_cn2[c0] - 2.f * dot.x;
            float d21 = xn2 + g_cn2[c0 + 1] - 2.f * dot.y;
            d2m = fminf(d20, d21);
        }
        float md2 = blk_min(d2m, red);
        float mh  = blk_max(fmaxf(hv0, hv1), red);
        float e0 = val ? __expf(hv0 - mh) : 0.f;
        float e1 = val ? __expf(hv1 - mh) : 0.f;
        float se = blk_sum(e0 + e1, red);
        if (tid < 512) {
            float inv = 1.f / se;
            float w0 = val ? e0 * inv : 0.f;
            float w1 = val ? e1 * inv : 0.f;
            uint32_t hp = f16pack(w0, w1);
            *(uint32_t*)&g_vmh[b * CP + c0] = hp;
            __half2 hh = *(__half2*)&hp;
            float l0 = w0 - __half2float(__low2half(hh));
            float l1 = w1 - __half2float(__high2half(hh));
            *(uint32_t*)&g_vml[b * CP + c0] = f16pack(l0, l1);
        }
        if (tid == 0) g_reach[b] = 10.f / sqrtf(fmaxf(md2, 1e-30f));
    }
    grid_sync(2);

    // ===== S3: memory_feature = vm @ centroids  (512 items, klen 64) =====
    {
        const int item = bid * 4 + gid;
        if (item < 32 * KSM) {
            const int nt = item & 31, ks = item >> 5;
            group_nn_f16(g_vmh, g_vml, CP, centroids, F_, g_p_mem[ks], F_,
                         nt * 64, ks * 64, 64, gsm, gt, barid);
        }
    }
    grid_sync(3);

    // ===== S4: feat = reach*(x + tanh(sel)*mem) on 128 blocks (half row each) =====
    if (bid < 128) {
        const int b = bid >> 1;
        const int f = (bid & 1) * 1024 + tid;
        const float reach = g_reach[b];
        float mem = 0.f, sz = 0.f;
#pragma unroll
        for (int s = 0; s < KSM; s++) mem += g_p_mem[s][b * F_ + f];
#pragma unroll
        for (int s = 0; s < KSA; s++) sz  += g_p_sel[s][b * F_ + f];
        float sel  = tanhf(sz + b_sel[f]);
        float xv   = x[(size_t)b * F_ + f];
        float inf  = sel * mem;
        float feat = reach * (xv + inf);
        __half fh, fl;
        hilo1(feat, fh, fl);
        g_fh[b * F_ + f] = fh;
        g_fl[b * F_ + f] = fl;
        if (writeFeat) {
            out[64000 + b * F_ + f]  = xv;   // direct_feature
            out[195072 + b * F_ + f] = inf;  // infused_feature
        }
        float n2 = blk_sum(feat * feat, red);
        if (tid == 0) g_n2p[bid] = n2;
    }
    grid_sync(4);

    // ===== S5: cos logits GEMM feat @ W_cos^T (512 items) + scale reduce on idle block =====
    {
        const int item = bid * 4 + gid;
        if (item < 16 * KSC) {
            const int nt = item & 15, ks = item >> 4;
            group_nt_f16(g_fh, g_fl, F_, W_cos, F_, g_p_cos[ks], CP, C_,
                         nt * 64, ks * 64, 64, gsm, gt, barid);
        }
    }
    if (bid == NB - 1 && tid < B_) {
        float n2 = g_n2p[2 * tid] + g_n2p[2 * tid + 1];
        g_scale[tid] = 16.f / (1.f + sqrtf(n2));
    }
    grid_sync(5);

    // ===== S6: final scaled logits =====
    {
        const int i = bid * 1024 + tid;
        if (i < B_ * C_) {
            const int b = i / C_, c = i - b * C_;
            float s = 0.f;
#pragma unroll
            for (int ss = 0; ss < KSC; ss++) s += g_p_cos[ss][b * CP + c];
            out[i] = s * g_scale[b] / g_wn[c];
        }
    }
}

// ================= launch =================
#define DSM_BYTES (4 * 2 * GRP * 2)   // 4 groups * 2 buffers * 3 arrays * 64*40 halves = 122880 B

extern "C" void kernel_launch(void* const* d_in, const int* in_sizes, int n_in,
                              void* d_out, int out_size) {
    const float* x         = (const float*)d_in[0];
    const float* centroids = (const float*)d_in[1];
    const float* W_hall    = (const float*)d_in[2];
    const float* b_hall    = (const float*)d_in[3];
    const float* W_sel     = (const float*)d_in[4];
    const float* b_sel     = (const float*)d_in[5];
    const float* W_cos     = (const float*)d_in[6];
    float* out = (float*)d_out;

    cudaFuncSetAttribute(fused_all, cudaFuncAttributeMaxDynamicSharedMemorySize, DSM_BYTES);

    int writeFeat = (out_size >= 326144) ? 1 : 0;
    fused_all<<<NB, 1024, DSM_BYTES>>>(x, centroids, W_hall, b_hall, W_sel, b_sel, W_cos,
                                       out, writeFeat);
}

// round 11
// speedup vs baseline: 2.5162x; 1.0829x over previous
#include <cuda_runtime.h>
#include <cuda_fp16.h>
#include <math.h>
#include <stdint.h>

#define B_   64
#define C_   1000
#define F_   2048
#define CP   1024
#define NB   148
#define KSA  8
#define KSM  16
#define KSC  32
#define KT   32
#define GA   (64 * 40)          // halves per tile array (row stride 40)
#define GRP  (3 * GA)           // Ah, Al, Bh per buffer
typedef unsigned long long ull;

// ---------------- scratch ----------------
__device__ __align__(256) float g_p_dot[KSA][B_ * CP];
__device__ __align__(256) float g_p_hall[KSA][B_ * CP];
__device__ __align__(256) float g_p_sel[KSA][B_ * F_];
__device__ __align__(256) float g_p_mem[KSM][B_ * F_];
__device__ __align__(256) float g_p_cos[KSC][B_ * CP];
__device__ __align__(256) __half g_xh[B_ * F_];
__device__ __align__(256) __half g_xl[B_ * F_];
__device__ __align__(256) __half g_vmh[B_ * CP];
__device__ __align__(256) __half g_vml[B_ * CP];
__device__ __align__(256) __half g_fh[B_ * F_];
__device__ __align__(256) __half g_fl[B_ * F_];
__device__ float g_cn2[CP];
__device__ float g_wn[CP];
__device__ float g_xn2[B_];
__device__ float g_reach[B_];
__device__ float g_scale[B_];
__device__ float g_n2p[128];
__device__ unsigned int g_arr[8];
__device__ unsigned int g_flag[8];

// ---------------- barriers / async ----------------
__device__ __forceinline__ void gbar(int id) {
    asm volatile("bar.sync %0, 256;" :: "r"(id) : "memory");
}
__device__ __forceinline__ uint32_t sm32(const void* p) {
    return (uint32_t)__cvta_generic_to_shared(p);
}
#define CPA16(sm, gp)  asm volatile("cp.async.cg.shared.global [%0], [%1], 16;" :: "r"(sm), "l"(gp))
#define CPCOMMIT()     asm volatile("cp.async.commit_group;" ::: "memory")
#define CPWAIT1()      asm volatile("cp.async.wait_group 1;" ::: "memory")

__device__ __forceinline__ void grid_sync(int s) {
    __threadfence();
    __syncthreads();
    if (threadIdx.x == 0) {
        unsigned int before = atomicOr(&g_flag[s], 0u);
        unsigned int old = atomicAdd(&g_arr[s], 1u);
        if (old == NB - 1) {
            g_arr[s] = 0;
            __threadfence();
            atomicAdd(&g_flag[s], 1u);
        } else {
            while (atomicOr(&g_flag[s], 0u) == before) __nanosleep(64);
        }
    }
    __syncthreads();
    __threadfence();
}

// ---------------- block reductions (1024 threads) ----------------
__device__ __forceinline__ float blk_sum(float v, float* red) {
#pragma unroll
    for (int o = 16; o; o >>= 1) v += __shfl_xor_sync(0xffffffffu, v, o);
    if ((threadIdx.x & 31) == 0) red[threadIdx.x >> 5] = v;
    __syncthreads();
    if (threadIdx.x < 32) {
        float s = red[threadIdx.x];
#pragma unroll
        for (int o = 16; o; o >>= 1) s += __shfl_xor_sync(0xffffffffu, s, o);
        if (threadIdx.x == 0) red[0] = s;
    }
    __syncthreads();
    float r = red[0];
    __syncthreads();
    return r;
}
__device__ __forceinline__ float blk_min(float v, float* red) {
#pragma unroll
    for (int o = 16; o; o >>= 1) v = fminf(v, __shfl_xor_sync(0xffffffffu, v, o));
    if ((threadIdx.x & 31) == 0) red[threadIdx.x >> 5] = v;
    __syncthreads();
    if (threadIdx.x < 32) {
        float s = red[threadIdx.x];
#pragma unroll
        for (int o = 16; o; o >>= 1) s = fminf(s, __shfl_xor_sync(0xffffffffu, s, o));
        if (threadIdx.x == 0) red[0] = s;
    }
    __syncthreads();
    float r = red[0];
    __syncthreads();
    return r;
}
__device__ __forceinline__ float blk_max(float v, float* red) {
#pragma unroll
    for (int o = 16; o; o >>= 1) v = fmaxf(v, __shfl_xor_sync(0xffffffffu, v, o));
    if ((threadIdx.x & 31) == 0) red[threadIdx.x >> 5] = v;
    __syncthreads();
    if (threadIdx.x < 32) {
        float s = red[threadIdx.x];
#pragma unroll
        for (int o = 16; o; o >>= 1) s = fmaxf(s, __shfl_xor_sync(0xffffffffu, s, o));
        if (threadIdx.x == 0) red[0] = s;
    }
    __syncthreads();
    float r = red[0];
    __syncthreads();
    return r;
}

// ---------------- fp16 helpers ----------------
__device__ __forceinline__ uint32_t f16pack(float lo, float hi) {
    uint32_t r;
    asm("cvt.rn.f16x2.f32 %0, %1, %2;" : "=r"(r) : "f"(hi), "f"(lo));
    return r;
}
__device__ __forceinline__ void hilo1(float v, __half& h, __half& l) {
    h = __float2half_rn(v);
    l = __float2half_rn(v - __half2float(h));
}
__device__ __forceinline__ void mma16816(float* d,
                                         uint32_t a0, uint32_t a1, uint32_t a2, uint32_t a3,
                                         uint32_t b0, uint32_t b1) {
    asm volatile("mma.sync.aligned.m16n8k16.row.col.f32.f16.f16.f32 "
        "{%0,%1,%2,%3}, {%4,%5,%6,%7}, {%8,%9}, {%0,%1,%2,%3};"
        : "+f"(d[0]), "+f"(d[1]), "+f"(d[2]), "+f"(d[3])
        : "r"(a0), "r"(a1), "r"(a2), "r"(a3), "r"(b0), "r"(b1));
}

// ---------------- mma over one 64x64x32 tile: acc += (Ah+Al)*Bh ----------------
__device__ __forceinline__ void tile_f16(const __half* buf, int m0, int nh,
                                         int fr, int fc, float acc[4][4]) {
    const __half* Ah = buf;
    const __half* Al = buf + GA;
    const __half* Bh = buf + 2 * GA;
#pragma unroll
    for (int kk = 0; kk < 2; kk++) {
        const int kc = kk * 16 + fc;
        uint32_t ah0 = *(const uint32_t*)&Ah[(m0 + fr) * 40 + kc];
        uint32_t ah1 = *(const uint32_t*)&Ah[(m0 + fr + 8) * 40 + kc];
        uint32_t ah2 = *(const uint32_t*)&Ah[(m0 + fr) * 40 + kc + 8];
        uint32_t ah3 = *(const uint32_t*)&Ah[(m0 + fr + 8) * 40 + kc + 8];
        uint32_t al0 = *(const uint32_t*)&Al[(m0 + fr) * 40 + kc];
        uint32_t al1 = *(const uint32_t*)&Al[(m0 + fr + 8) * 40 + kc];
        uint32_t al2 = *(const uint32_t*)&Al[(m0 + fr) * 40 + kc + 8];
        uint32_t al3 = *(const uint32_t*)&Al[(m0 + fr + 8) * 40 + kc + 8];
#pragma unroll
        for (int nt = 0; nt < 4; nt++) {
            const int bn = (nh + nt * 8 + fr) * 40;
            uint32_t bh0 = *(const uint32_t*)&Bh[bn + kc];
            uint32_t bh1 = *(const uint32_t*)&Bh[bn + kc + 8];
            mma16816(acc[nt], ah0, ah1, ah2, ah3, bh0, bh1);
            mma16816(acc[nt], al0, al1, al2, al3, bh0, bh1);
        }
    }
}

__device__ __forceinline__ void store_acc(float* __restrict__ P, int ldp, int n0,
                                          int m0, int nh, int fr, int fc,
                                          float acc[4][4]) {
#pragma unroll
    for (int nt = 0; nt < 4; nt++) {
        const int n = n0 + nh + nt * 8 + fc;
        *(float2*)&P[(size_t)(m0 + fr) * ldp + n]     = make_float2(acc[nt][0], acc[nt][1]);
        *(float2*)&P[(size_t)(m0 + fr + 8) * ldp + n] = make_float2(acc[nt][2], acc[nt][3]);
    }
}

// NT: P = A(fp16 h/l precomputed) @ B(fp32, cvt hi-only)^T. 3-deep cp.async pipeline.
__device__ __forceinline__ void group_nt_f16(const __half* __restrict__ Ahg,
                                             const __half* __restrict__ Alg, int lda,
                                             const float* __restrict__ Bm, int ldb,
                                             float* __restrict__ P, int ldp,
                                             int Nn, int n0, int k0, int klen,
                                             __half* gsm, int gt, int barid) {
    const int lane = gt & 31, wg = gt >> 5;
    const int m0 = (wg & 3) * 16, nh = (wg >> 2) * 32;
    const int fr = lane >> 2, fc = (lane & 3) * 2;
    const int row = gt >> 2, kq = (gt & 3) * 8;
    const bool bv = (n0 + row) < Nn;
    const __half* Ah_p = Ahg + (size_t)row * lda + k0 + kq;
    const __half* Al_p = Alg + (size_t)row * lda + k0 + kq;
    const float*  B_p  = Bm + (size_t)(n0 + row) * ldb + k0 + kq;
    const int T = klen >> 5;
    const uint32_t base32 = sm32(gsm);
    const uint32_t offA = (uint32_t)(row * 40 + kq) * 2;

    float acc[4][4];
#pragma unroll
    for (int i = 0; i < 4; i++)
#pragma unroll
        for (int j = 0; j < 4; j++) acc[i][j] = 0.f;

    float4 pb0, pb1;
    auto ldB = [&](int t) {
        if (bv) { pb0 = *(const float4*)(B_p + t * KT); pb1 = *(const float4*)(B_p + t * KT + 4); }
        else    { pb0 = make_float4(0,0,0,0); pb1 = pb0; }
    };
    auto stB = [&](int bufi) {
        uint4 bp = make_uint4(f16pack(pb0.x, pb0.y), f16pack(pb0.z, pb0.w),
                              f16pack(pb1.x, pb1.y), f16pack(pb1.z, pb1.w));
        *(uint4*)(gsm + bufi * GRP + 2 * GA + row * 40 + kq) = bp;
    };
    auto cpA = [&](int bufi, int t) {
        uint32_t b = base32 + (uint32_t)bufi * (GRP * 2) + offA;
        CPA16(b, Ah_p + t * KT);
        CPA16(b + GA * 2, Al_p + t * KT);
    };

    // prologue (T >= 2 always)
    cpA(0, 0); CPCOMMIT();
    cpA(1, 1); CPCOMMIT();
    ldB(0); stB(0);
    ldB(1);
    CPWAIT1();
    gbar(barid);

    int cur = 0;
    for (int t = 0; t < T; t++) {
        int nx2 = cur + 2; if (nx2 >= 3) nx2 -= 3;
        if (t + 2 < T) cpA(nx2, t + 2);
        CPCOMMIT();
        tile_f16(gsm + cur * GRP, m0, nh, fr, fc, acc);
        if (t + 1 < T) {
            int nx = cur + 1; if (nx == 3) nx = 0;
            stB(nx);
            if (t + 2 < T) ldB(t + 2);
            CPWAIT1();
            gbar(barid);
        }
        cur = cur + 1; if (cur == 3) cur = 0;
    }
    store_acc(P, ldp, n0, m0, nh, fr, fc, acc);
}

// NN: P = A(fp16 h/l) @ B(fp32 k-major, cvt + transpose hi-only). 3-deep pipeline.
__device__ __forceinline__ void group_nn_f16(const __half* __restrict__ Ahg,
                                             const __half* __restrict__ Alg, int lda,
                                             const float* __restrict__ Bm, int ldb,
                                             float* __restrict__ P, int ldp,
                                             int n0, int k0, int klen,
                                             __half* gsm, int gt, int barid) {
    const int lane = gt & 31, wg = gt >> 5;
    const int m0 = (wg & 3) * 16, nh = (wg >> 2) * 32;
    const int fr = lane >> 2, fc = (lane & 3) * 2;
    const int row = gt >> 2, kq = (gt & 3) * 8;
    const int k2 = (gt & 15) * 2, nq = (gt >> 4) * 4;
    const __half* Ah_p = Ahg + (size_t)row * lda + k0 + kq;
    const __half* Al_p = Alg + (size_t)row * lda + k0 + kq;
    const int T = klen >> 5;
    const uint32_t base32 = sm32(gsm);
    const uint32_t offA = (uint32_t)(row * 40 + kq) * 2;

    float acc[4][4];
#pragma unroll
    for (int i = 0; i < 4; i++)
#pragma unroll
        for (int j = 0; j < 4; j++) acc[i][j] = 0.f;

    float4 pb0, pb1;
    auto ldB = [&](int t) {
        int kr0 = k0 + t * KT + k2;
        pb0 = (kr0 < C_)     ? *(const float4*)&Bm[(size_t)kr0 * ldb + n0 + nq]       : make_float4(0,0,0,0);
        pb1 = (kr0 + 1 < C_) ? *(const float4*)&Bm[(size_t)(kr0 + 1) * ldb + n0 + nq] : make_float4(0,0,0,0);
    };
    auto stB = [&](int bufi) {
        __half* Bh = gsm + bufi * GRP + 2 * GA;
        *(uint32_t*)&Bh[(nq + 0) * 40 + k2] = f16pack(pb0.x, pb1.x);
        *(uint32_t*)&Bh[(nq + 1) * 40 + k2] = f16pack(pb0.y, pb1.y);
        *(uint32_t*)&Bh[(nq + 2) * 40 + k2] = f16pack(pb0.z, pb1.z);
        *(uint32_t*)&Bh[(nq + 3) * 40 + k2] = f16pack(pb0.w, pb1.w);
    };
    auto cpA = [&](int bufi, int t) {
        uint32_t b = base32 + (uint32_t)bufi * (GRP * 2) + offA;
        CPA16(b, Ah_p + t * KT);
        CPA16(b + GA * 2, Al_p + t * KT);
    };

    cpA(0, 0); CPCOMMIT();
    cpA(1, 1); CPCOMMIT();
    ldB(0); stB(0);
    ldB(1);
    CPWAIT1();
    gbar(barid);

    int cur = 0;
    for (int t = 0; t < T; t++) {
        int nx2 = cur + 2; if (nx2 >= 3) nx2 -= 3;
        if (t + 2 < T) cpA(nx2, t + 2);
        CPCOMMIT();
        tile_f16(gsm + cur * GRP, m0, nh, fr, fc, acc);
        if (t + 1 < T) {
            int nx = cur + 1; if (nx == 3) nx = 0;
            stB(nx);
            if (t + 2 < T) ldB(t + 2);
            CPWAIT1();
            gbar(barid);
        }
        cur = cur + 1; if (cur == 3) cur = 0;
    }
    store_acc(P, ldp, n0, m0, nh, fr, fc, acc);
}

// ---------------- the single fused persistent kernel ----------------
__global__ void __launch_bounds__(1024, 1)
fused_all(const float* __restrict__ x,
          const float* __restrict__ centroids,
          const float* __restrict__ W_hall,
          const float* __restrict__ b_hall,
          const float* __restrict__ W_sel,
          const float* __restrict__ b_sel,
          const float* __restrict__ W_cos,
          float* __restrict__ out, int writeFeat) {
    extern __shared__ __align__(16) __half dsm[];   // 4 groups * 3 buffers * GRP
    __shared__ float red[32];
    const int tid = threadIdx.x, bid = blockIdx.x;
    const int gid = tid >> 8, gt = tid & 255, barid = gid + 1;
    __half* gsm = dsm + gid * 3 * GRP;

    // ===== S0a: x -> fp16 hi/lo =====
    {
        const int i = bid * 1024 + tid;
        if (i < B_ * F_) {
            __half h, l;
            hilo1(x[i], h, l);
            g_xh[i] = h; g_xl[i] = l;
        }
    }
    // ===== S0b: row norms (one row per warp) =====
    {
        const int gw = bid * 32 + (tid >> 5);
        const int lane = tid & 31;
        if (gw < 2064) {
            const float* src; int mode, idx;
            if (gw < 1000)      { src = centroids + (size_t)gw * F_;      mode = 0; idx = gw; }
            else if (gw < 2000) { src = W_cos + (size_t)(gw - 1000) * F_; mode = 1; idx = gw - 1000; }
            else                { src = x + (size_t)(gw - 2000) * F_;     mode = 2; idx = gw - 2000; }
            const float4* s4 = (const float4*)src;
            float s = 0.f;
            for (int i = lane; i < F_ / 4; i += 32) {
                float4 v = s4[i];
                s += v.x * v.x + v.y * v.y + v.z * v.z + v.w * v.w;
            }
#pragma unroll
            for (int o = 16; o; o >>= 1) s += __shfl_xor_sync(0xffffffffu, s, o);
            if (lane == 0) {
                if (mode == 0)      g_cn2[idx] = s;
                else if (mode == 1) g_wn[idx]  = sqrtf(s);
                else                g_xn2[idx] = s;
            }
        }
    }
    grid_sync(0);

    // ===== S1: mega GEMMs x @ [centroids; W_hall; W_sel]^T  (512 items, klen 256) =====
    {
        const int item = bid * 4 + gid;
        if (item < 64 * KSA) {
            const int t = item & 63, ks = item >> 6;
            const float* Bm; float* P; int Nn, n0, ldp;
            if (t < 16)      { Bm = centroids; P = g_p_dot[ks];  Nn = C_; n0 = t * 64;        ldp = CP; }
            else if (t < 32) { Bm = W_hall;    P = g_p_hall[ks]; Nn = C_; n0 = (t - 16) * 64; ldp = CP; }
            else             { Bm = W_sel;     P = g_p_sel[ks];  Nn = F_; n0 = (t - 32) * 64; ldp = F_; }
            group_nt_f16(g_xh, g_xl, F_, Bm, F_, P, ldp, Nn, n0, ks * 256, 256, gsm, gt, barid);
        }
    }
    grid_sync(1);

    // ===== S2: reduce dot/hall, min-dist, softmax, reachability (64 blocks) =====
    if (bid < B_) {
        const int b = bid;
        const int c0 = tid * 2;
        const bool val = (tid < 500);
        float hv0 = -1e30f, hv1 = -1e30f, d2m = 1e30f;
        if (val) {
            float2 dot = make_float2(0.f, 0.f), h = make_float2(0.f, 0.f);
#pragma unroll
            for (int s = 0; s < KSA; s++) {
                float2 d = *(const float2*)&g_p_dot[s][b * CP + c0];
                float2 hh = *(const float2*)&g_p_hall[s][b * CP + c0];
                dot.x += d.x; dot.y += d.y; h.x += hh.x; h.y += hh.y;
            }
            float2 bh = *(const float2*)&b_hall[c0];
            hv0 = h.x + bh.x; hv1 = h.y + bh.y;
            float xn2 = g_xn2[b];
            float d20 = xn2 + g_cn2[c0] - 2.f * dot.x;
            float d21 = xn2 + g_cn2[c0 + 1] - 2.f * dot.y;
            d2m = fminf(d20, d21);
        }
        float md2 = blk_min(d2m, red);
        float mh  = blk_max(fmaxf(hv0, hv1), red);
        float e0 = val ? __expf(hv0 - mh) : 0.f;
        float e1 = val ? __expf(hv1 - mh) : 0.f;
        float se = blk_sum(e0 + e1, red);
        if (tid < 512) {
            float inv = 1.f / se;
            float w0 = val ? e0 * inv : 0.f;
            float w1 = val ? e1 * inv : 0.f;
            uint32_t hp = f16pack(w0, w1);
            *(uint32_t*)&g_vmh[b * CP + c0] = hp;
            __half2 hh = *(__half2*)&hp;
            float l0 = w0 - __half2float(__low2half(hh));
            float l1 = w1 - __half2float(__high2half(hh));
            *(uint32_t*)&g_vml[b * CP + c0] = f16pack(l0, l1);
        }
        if (tid == 0) g_reach[b] = 10.f / sqrtf(fmaxf(md2, 1e-30f));
    }
    grid_sync(2);

    // ===== S3: memory_feature = vm @ centroids  (512 items, klen 64) =====
    {
        const int item = bid * 4 + gid;
        if (item < 32 * KSM) {
            const int nt = item & 31, ks = item >> 5;
            group_nn_f16(g_vmh, g_vml, CP, centroids, F_, g_p_mem[ks], F_,
                         nt * 64, ks * 64, 64, gsm, gt, barid);
        }
    }
    grid_sync(3);

    // ===== S4: feat = reach*(x + tanh(sel)*mem) on 128 blocks (half row each) =====
    if (bid < 128) {
        const int b = bid >> 1;
        const int f = (bid & 1) * 1024 + tid;
        const float reach = g_reach[b];
        float mem = 0.f, sz = 0.f;
#pragma unroll
        for (int s = 0; s < KSM; s++) mem += g_p_mem[s][b * F_ + f];
#pragma unroll
        for (int s = 0; s < KSA; s++) sz  += g_p_sel[s][b * F_ + f];
        float sel  = tanhf(sz + b_sel[f]);
        float xv   = x[(size_t)b * F_ + f];
        float inf  = sel * mem;
        float feat = reach * (xv + inf);
        __half fh, fl;
        hilo1(feat, fh, fl);
        g_fh[b * F_ + f] = fh;
        g_fl[b * F_ + f] = fl;
        if (writeFeat) {
            out[64000 + b * F_ + f]  = xv;   // direct_feature
            out[195072 + b * F_ + f] = inf;  // infused_feature
        }
        float n2 = blk_sum(feat * feat, red);
        if (tid == 0) g_n2p[bid] = n2;
    }
    grid_sync(4);

    // ===== S5: cos logits GEMM feat @ W_cos^T (512 items) + scale reduce on idle block =====
    {
        const int item = bid * 4 + gid;
        if (item < 16 * KSC) {
            const int nt = item & 15, ks = item >> 4;
            group_nt_f16(g_fh, g_fl, F_, W_cos, F_, g_p_cos[ks], CP, C_,
                         nt * 64, ks * 64, 64, gsm, gt, barid);
        }
    }
    if (bid == NB - 1 && tid < B_) {
        float n2 = g_n2p[2 * tid] + g_n2p[2 * tid + 1];
        g_scale[tid] = 16.f / (1.f + sqrtf(n2));
    }
    grid_sync(5);

    // ===== S6: final scaled logits =====
    {
        const int i = bid * 1024 + tid;
        if (i < B_ * C_) {
            const int b = i / C_, c = i - b * C_;
            float s = 0.f;
#pragma unroll
            for (int ss = 0; ss < KSC; ss++) s += g_p_cos[ss][b * CP + c];
            out[i] = s * g_scale[b] / g_wn[c];
        }
    }
}

// ================= launch =================
#define DSM_BYTES (4 * 3 * GRP * 2)   // 4 groups * 3 buffers * (3*64*40) halves = 184320 B

extern "C" void kernel_launch(void* const* d_in, const int* in_sizes, int n_in,
                              void* d_out, int out_size) {
    const float* x         = (const float*)d_in[0];
    const float* centroids = (const float*)d_in[1];
    const float* W_hall    = (const float*)d_in[2];
    const float* b_hall    = (const float*)d_in[3];
    const float* W_sel     = (const float*)d_in[4];
    const float* b_sel     = (const float*)d_in[5];
    const float* W_cos     = (const float*)d_in[6];
    float* out = (float*)d_out;

    cudaFuncSetAttribute(fused_all, cudaFuncAttributeMaxDynamicSharedMemorySize, DSM_BYTES);

    int writeFeat = (out_size >= 326144) ? 1 : 0;
    fused_all<<<NB, 1024, DSM_BYTES>>>(x, centroids, W_hall, b_hall, W_sel, b_sel, W_cos,
                                       out, writeFeat);
}